// round 11
// baseline (speedup 1.0000x reference)
#include <cuda_runtime.h>
#include <cuda_bf16.h>
#include <math.h>
#include <stdint.h>

// ---------------- problem constants ----------------
#define BATCH     2
#define SEQ       2048
#define TTOT      (BATCH*SEQ)        // 4096
#define DMODEL    1024
#define DINNER    2048
#define DHEAD     64
#define NHEADS    32
#define DSTATE    64
#define DCONV     4
#define CONVDIM   (DINNER + 2*DSTATE)            // 2176
#define DINPROJ   (2*DINNER + 2*DSTATE + NHEADS) // 4256
#define NLAYERS   4
#define EPSV      1e-5f

#define CHL       128                 // scan chunk length
#define NCH       (SEQ/CHL)           // 16 chunks per sequence
#define TT        8                   // scan timestep tile

// ---------------- scratch (device globals; no allocs allowed) ----------------
__device__ float g_zxbcdt[(size_t)TTOT * DINPROJ];
__device__ float g_xconv[(size_t)TTOT * CONVDIM];
__device__ float g_dt[(size_t)TTOT * NHEADS];
__device__ float g_y[(size_t)TTOT * DINNER];
__device__ __nv_bfloat16 g_asp[(size_t)TTOT * 3 * DINNER];    // A triplets
__device__ __nv_bfloat16 g_bsp[(size_t)DINPROJ * 3 * DMODEL]; // B triplets
__device__ float g_Sloc[(size_t)BATCH*NHEADS*NCH * DHEAD * DSTATE];
__device__ float g_Sin [(size_t)BATCH*NHEADS*NCH * DHEAD * DSTATE];
__device__ float g_cumdt[(size_t)TTOT * NHEADS];

__device__ __forceinline__ uint32_t s2u(const void* p) {
    return (uint32_t)__cvta_generic_to_shared(p);
}

// =========== bf16 mma.sync NT GEMM: C[M,N] = A[M,K'] @ B[N,K']^T (+C) =======
// Triplet operands: A row = [hi|lo|hi] (3K), B row = [hi|hi|lo] (3K).
// CTA tile 128x128, 4 warps (2x2), warp tile 64x64, BK=64, 3-stage cp.async.
// SMEM: 128 rows x 128B per operand per stage, XOR swizzle on 16B chunks.
#define BM 128
#define BN 128
#define BK 64
#define NSTG 3
#define STG_A 16384
#define STG_BYTES (2*STG_A)
#define GEMM_SMEM_BYTES (NSTG * STG_BYTES)   // 98304 B

__device__ __forceinline__ void gemm_issue(
    const __nv_bfloat16* __restrict__ A, const __nv_bfloat16* __restrict__ B,
    int N, int K, int m0, int n0, int kbase,
    char* As, char* Bs, int tid)
{
    #pragma unroll
    for (int it = 0; it < 8; it++) {
        int id  = tid + it * 128;      // 0..1023
        int row = id >> 3;
        int ch  = id & 7;
        int sw  = ch ^ (row & 7);
        int dst = row * 128 + sw * 16;
        {
            uint32_t saddr = s2u(As + dst);
            const void* g = A + (size_t)(m0 + row) * K + kbase + ch * 8;
            asm volatile("cp.async.cg.shared.global [%0], [%1], 16;"
                         :: "r"(saddr), "l"(g));
        }
        {
            uint32_t saddr = s2u(Bs + dst);
            int valid = (n0 + row) < N;
            const void* g = B + (valid ? ((size_t)(n0 + row) * K + kbase + ch * 8) : 0);
            int sz = valid ? 16 : 0;
            asm volatile("cp.async.cg.shared.global [%0], [%1], 16, %2;"
                         :: "r"(saddr), "l"(g), "r"(sz));
        }
    }
}

__global__ __launch_bounds__(128, 2)
void gemm_bf16_nt(const __nv_bfloat16* __restrict__ A, const __nv_bfloat16* __restrict__ B,
                  float* __restrict__ C, int M, int N, int K, int addC)
{
    extern __shared__ __align__(16) char dynsmem[];

    int tid  = threadIdx.x;
    int lane = tid & 31;
    int wid  = tid >> 5;               // 0..3
    int m0 = blockIdx.y * BM;
    int n0 = blockIdx.x * BN;
    int wm = (wid & 1) * 64;
    int wn = (wid >> 1) * 64;

    float acc[4][8][4];
    #pragma unroll
    for (int a = 0; a < 4; a++)
        #pragma unroll
        for (int b = 0; b < 8; b++)
            #pragma unroll
            for (int c = 0; c < 4; c++) acc[a][b][c] = 0.f;

    int NT = K / BK;

    #pragma unroll
    for (int s = 0; s < NSTG - 1; s++) {
        gemm_issue(A, B, N, K, m0, n0, s * BK,
                   dynsmem + s * STG_BYTES, dynsmem + s * STG_BYTES + STG_A, tid);
        asm volatile("cp.async.commit_group;" ::: "memory");
    }

    int sc = 0;
    int si = NSTG - 1;
    for (int kt = 0; kt < NT; kt++) {
        asm volatile("cp.async.wait_group 1;" ::: "memory");
        __syncthreads();
        if (kt + 2 < NT) {
            gemm_issue(A, B, N, K, m0, n0, (kt + 2) * BK,
                       dynsmem + si * STG_BYTES, dynsmem + si * STG_BYTES + STG_A, tid);
        }
        asm volatile("cp.async.commit_group;" ::: "memory");
        si = (si == NSTG - 1) ? 0 : si + 1;

        char* As = dynsmem + sc * STG_BYTES;
        char* Bs = As + STG_A;
        sc = (sc == NSTG - 1) ? 0 : sc + 1;

        #pragma unroll
        for (int ks = 0; ks < 4; ks++) {
            uint32_t af[4][4];
            uint32_t bf[8][2];
            #pragma unroll
            for (int mi = 0; mi < 4; mi++) {
                int row = wm + mi * 16 + (lane & 15);
                int ch  = ks * 2 + (lane >> 4);
                int sw  = ch ^ (row & 7);
                uint32_t addr = s2u(As + row * 128 + sw * 16);
                asm volatile("ldmatrix.sync.aligned.m8n8.x4.shared.b16 {%0,%1,%2,%3}, [%4];"
                             : "=r"(af[mi][0]), "=r"(af[mi][1]),
                               "=r"(af[mi][2]), "=r"(af[mi][3])
                             : "r"(addr));
            }
            #pragma unroll
            for (int nj = 0; nj < 8; nj += 2) {
                int row = wn + nj * 8 + (lane >> 4) * 8 + (lane & 7);
                int ch  = ks * 2 + ((lane >> 3) & 1);
                int sw  = ch ^ (row & 7);
                uint32_t addr = s2u(Bs + row * 128 + sw * 16);
                asm volatile("ldmatrix.sync.aligned.m8n8.x4.shared.b16 {%0,%1,%2,%3}, [%4];"
                             : "=r"(bf[nj][0]), "=r"(bf[nj][1]),
                               "=r"(bf[nj + 1][0]), "=r"(bf[nj + 1][1])
                             : "r"(addr));
            }
            #pragma unroll
            for (int mi = 0; mi < 4; mi++)
                #pragma unroll
                for (int nj = 0; nj < 8; nj++)
                    asm volatile(
                        "mma.sync.aligned.m16n8k16.row.col.f32.bf16.bf16.f32 "
                        "{%0,%1,%2,%3}, {%4,%5,%6,%7}, {%8,%9}, {%0,%1,%2,%3};"
                        : "+f"(acc[mi][nj][0]), "+f"(acc[mi][nj][1]),
                          "+f"(acc[mi][nj][2]), "+f"(acc[mi][nj][3])
                        : "r"(af[mi][0]), "r"(af[mi][1]),
                          "r"(af[mi][2]), "r"(af[mi][3]),
                          "r"(bf[nj][0]), "r"(bf[nj][1]));
        }
    }

    #pragma unroll
    for (int mi = 0; mi < 4; mi++) {
        int r0 = m0 + wm + mi * 16 + (lane >> 2);
        #pragma unroll
        for (int nj = 0; nj < 8; nj++) {
            int c0 = n0 + wn + nj * 8 + (lane & 3) * 2;
            if (c0 < N) {
                float2* p0 = (float2*)(C + (size_t)r0 * N + c0);
                float2* p1 = (float2*)(C + (size_t)(r0 + 8) * N + c0);
                float2 v0 = make_float2(acc[mi][nj][0], acc[mi][nj][1]);
                float2 v1 = make_float2(acc[mi][nj][2], acc[mi][nj][3]);
                if (addC) {
                    float2 o0 = *p0, o1 = *p1;
                    v0.x += o0.x; v0.y += o0.y;
                    v1.x += o1.x; v1.y += o1.y;
                }
                *p0 = v0;
                *p1 = v1;
            }
        }
    }
}

// ---------------- rmsnorm + bf16 triplet split ([hi,lo,hi]), float4 ---------
__global__ void rmsnorm_split_kernel(const float* __restrict__ x,
                                     const float* __restrict__ w,
                                     __nv_bfloat16* __restrict__ O)
{
    int t = blockIdx.x;
    int tid = threadIdx.x;
    const float4* xr4 = (const float4*)(x + (size_t)t * DMODEL);
    float4 v = xr4[tid];
    float lsum = v.x * v.x + v.y * v.y + v.z * v.z + v.w * v.w;

    __shared__ float wsum[8];
    int lane = tid & 31, wid = tid >> 5;
    #pragma unroll
    for (int off = 16; off > 0; off >>= 1)
        lsum += __shfl_xor_sync(0xffffffffu, lsum, off);
    if (lane == 0) wsum[wid] = lsum;
    __syncthreads();
    __shared__ float s_rs;
    if (tid == 0) {
        float tot = 0.f;
        for (int i = 0; i < 8; i++) tot += wsum[i];
        s_rs = rsqrtf(tot / (float)DMODEL + EPSV);
    }
    __syncthreads();
    float rs = s_rs;
    float4 wv = ((const float4*)w)[tid];
    float o[4] = {v.x * rs * wv.x, v.y * rs * wv.y, v.z * rs * wv.z, v.w * rs * wv.w};
    __nv_bfloat16 hi[4], lo[4];
    #pragma unroll
    for (int j = 0; j < 4; j++) {
        hi[j] = __float2bfloat16(o[j]);
        lo[j] = __float2bfloat16(o[j] - __bfloat162float(hi[j]));
    }
    __nv_bfloat16* orow = O + (size_t)t * (3 * DMODEL) + tid * 4;
    __nv_bfloat162* p0 = (__nv_bfloat162*)orow;
    __nv_bfloat162* p1 = (__nv_bfloat162*)(orow + DMODEL);
    __nv_bfloat162* p2 = (__nv_bfloat162*)(orow + 2 * DMODEL);
    p0[0] = __nv_bfloat162{hi[0], hi[1]};  p0[1] = __nv_bfloat162{hi[2], hi[3]};
    p1[0] = __nv_bfloat162{lo[0], lo[1]};  p1[1] = __nv_bfloat162{lo[2], lo[3]};
    p2[0] = __nv_bfloat162{hi[0], hi[1]};  p2[1] = __nv_bfloat162{hi[2], hi[3]};
}

// ---------------- weight split: fp32 -> [hi, hi, lo] triplet, float4 --------
__global__ void split_w_kernel(const float* __restrict__ X, __nv_bfloat16* __restrict__ O,
                               int rows, int K)
{
    int i4 = blockIdx.x * blockDim.x + threadIdx.x;
    int kq = K >> 2;
    if (i4 >= rows * kq) return;
    int r = i4 / kq;
    int k = (i4 - r * kq) * 4;
    float4 x = ((const float4*)X)[i4];
    float xv[4] = {x.x, x.y, x.z, x.w};
    __nv_bfloat16 hi[4], lo[4];
    #pragma unroll
    for (int j = 0; j < 4; j++) {
        hi[j] = __float2bfloat16(xv[j]);
        lo[j] = __float2bfloat16(xv[j] - __bfloat162float(hi[j]));
    }
    __nv_bfloat16* orow = O + (size_t)r * (3 * K) + k;
    __nv_bfloat162* p0 = (__nv_bfloat162*)orow;
    __nv_bfloat162* p1 = (__nv_bfloat162*)(orow + K);
    __nv_bfloat162* p2 = (__nv_bfloat162*)(orow + 2 * K);
    p0[0] = __nv_bfloat162{hi[0], hi[1]};  p0[1] = __nv_bfloat162{hi[2], hi[3]};
    p1[0] = __nv_bfloat162{hi[0], hi[1]};  p1[1] = __nv_bfloat162{hi[2], hi[3]};
    p2[0] = __nv_bfloat162{lo[0], lo[1]};  p2[1] = __nv_bfloat162{lo[2], lo[3]};
}

// ---------------- depthwise conv(4) + silu: 2 timesteps per thread ----------
__global__ void conv_silu_kernel(const float* __restrict__ zxbcdt,
                                 const float* __restrict__ cw,
                                 const float* __restrict__ cb,
                                 float* __restrict__ xconv)
{
    const int NC4 = CONVDIM / 4;
    int i = blockIdx.x * blockDim.x + threadIdx.x;
    if (i >= (TTOT / 2) * NC4) return;
    int c4 = i % NC4;
    int tp = i / NC4;
    int b  = tp / (SEQ / 2);
    int l0 = (tp % (SEQ / 2)) * 2;
    int ch = c4 * 4;

    float wk[DCONV][4];
    #pragma unroll
    for (int j = 0; j < 4; j++) {
        float4 w = *(const float4*)(cw + (ch + j) * DCONV);
        wk[0][j] = w.x; wk[1][j] = w.y; wk[2][j] = w.z; wk[3][j] = w.w;
    }
    float4 bb = *(const float4*)(cb + ch);

    float4 in[5];
    #pragma unroll
    for (int k = 0; k < 5; k++) {
        int ll = l0 - 3 + k;
        if (ll >= 0)
            in[k] = *(const float4*)(zxbcdt + (size_t)(b * SEQ + ll) * DINPROJ + DINNER + ch);
        else
            in[k] = make_float4(0.f, 0.f, 0.f, 0.f);
    }

    float a0[4] = {bb.x, bb.y, bb.z, bb.w};
    float a1[4] = {bb.x, bb.y, bb.z, bb.w};
    #pragma unroll
    for (int k = 0; k < DCONV; k++) {
        float* v0 = (float*)&in[k];
        float* v1 = (float*)&in[k + 1];
        #pragma unroll
        for (int j = 0; j < 4; j++) {
            a0[j] = fmaf(v0[j], wk[k][j], a0[j]);
            a1[j] = fmaf(v1[j], wk[k][j], a1[j]);
        }
    }
    float4 o0, o1;
    o0.x = a0[0] / (1.f + __expf(-a0[0]));
    o0.y = a0[1] / (1.f + __expf(-a0[1]));
    o0.z = a0[2] / (1.f + __expf(-a0[2]));
    o0.w = a0[3] / (1.f + __expf(-a0[3]));
    o1.x = a1[0] / (1.f + __expf(-a1[0]));
    o1.y = a1[1] / (1.f + __expf(-a1[1]));
    o1.z = a1[2] / (1.f + __expf(-a1[2]));
    o1.w = a1[3] / (1.f + __expf(-a1[3]));
    *(float4*)(xconv + (size_t)(b * SEQ + l0) * CONVDIM + ch)     = o0;
    *(float4*)(xconv + (size_t)(b * SEQ + l0 + 1) * CONVDIM + ch) = o1;
}

// ---------------- dt softplus ----------------
__global__ void dt_softplus_kernel(const float* __restrict__ zxbcdt,
                                   const float* __restrict__ dt_bias,
                                   float* __restrict__ dtout)
{
    int i = blockIdx.x * blockDim.x + threadIdx.x;
    if (i >= TTOT * NHEADS) return;
    int t = i >> 5;
    int h = i & 31;
    float v = zxbcdt[(size_t)t * DINPROJ + (DINPROJ - NHEADS) + h] + dt_bias[h];
    dtout[i] = (v > 20.f) ? v : log1pf(__expf(v));
}

// ---------------- SSD phase A: local chunk scans, 8-step tiles ---------------
// thread = (p, quad); quad owns n = quad*4 + j4*16 + jj (conflict-free LDS.128).
__global__ __launch_bounds__(256, 4)
void ssd_local_kernel(const float* __restrict__ xconv,
                      const float* __restrict__ dt,
                      const float* __restrict__ A_log,
                      const float* __restrict__ Dvec,
                      float* __restrict__ y,
                      float* __restrict__ Sloc,
                      float* __restrict__ cumdt)
{
    int bhc = blockIdx.x;
    int c = bhc & (NCH - 1);
    int h = (bhc >> 4) & 31;
    int b = bhc >> 9;
    float A  = -__expf(A_log[h]);
    float Dh = Dvec[h];
    int tid  = threadIdx.x;
    int lane = tid & 31;
    int wrp  = tid >> 5;
    int p    = tid >> 2;
    int quad = tid & 3;
    int q4   = quad * 4;

    __shared__ float sB[TT][DSTATE], sC[TT][DSTATE], sX[TT][DHEAD];
    __shared__ float sdt[TT];

    float s[16];
    #pragma unroll
    for (int j = 0; j < 16; j++) s[j] = 0.f;
    float cum = 0.f;
    int tbase = b * SEQ + c * CHL;

    for (int t0 = 0; t0 < CHL; t0 += TT) {
        {
            const float* row = xconv + (size_t)(tbase + t0 + wrp) * CONVDIM;
            sB[wrp][lane]      = row[DINNER + lane];
            sB[wrp][lane + 32] = row[DINNER + lane + 32];
            sC[wrp][lane]      = row[DINNER + DSTATE + lane];
            sC[wrp][lane + 32] = row[DINNER + DSTATE + lane + 32];
            sX[wrp][lane]      = row[h * DHEAD + lane];
            sX[wrp][lane + 32] = row[h * DHEAD + lane + 32];
        }
        if (tid < TT) sdt[tid] = dt[(size_t)(tbase + t0 + tid) * NHEADS + h];
        __syncthreads();

        if (tid == 0) {
            float cc = cum;
            #pragma unroll
            for (int w = 0; w < TT; w++) {
                cc += sdt[w];
                cumdt[(size_t)(tbase + t0 + w) * NHEADS + h] = cc;
            }
            cum = cc;
        }

        #pragma unroll
        for (int w = 0; w < TT; w++) {
            float dts = sdt[w];
            float da  = __expf(dts * A);
            float xp  = sX[w][p] * dts;
            float accv = 0.f;
            #pragma unroll
            for (int j4 = 0; j4 < 4; j4++) {
                float4 bv = *(const float4*)&sB[w][q4 + j4 * 16];
                float4 cv = *(const float4*)&sC[w][q4 + j4 * 16];
                float* bvp = (float*)&bv;
                float* cvp = (float*)&cv;
                #pragma unroll
                for (int jj = 0; jj < 4; jj++) {
                    int idx = j4 * 4 + jj;
                    s[idx] = fmaf(da, s[idx], xp * bvp[jj]);
                    accv   = fmaf(cvp[jj], s[idx], accv);
                }
            }
            accv += __shfl_xor_sync(0xffffffffu, accv, 1);
            accv += __shfl_xor_sync(0xffffffffu, accv, 2);
            if (quad == 0)
                y[(size_t)(tbase + t0 + w) * DINNER + h * DHEAD + p] = accv + Dh * sX[w][p];
        }
        __syncthreads();
    }

    float* sl = Sloc + ((size_t)bhc * DHEAD + p) * DSTATE + q4;
    #pragma unroll
    for (int j4 = 0; j4 < 4; j4++)
        *(float4*)(sl + j4 * 16) = make_float4(s[j4 * 4], s[j4 * 4 + 1],
                                               s[j4 * 4 + 2], s[j4 * 4 + 3]);
}

// ---------------- SSD phase B: sequential carry combine over chunks ----------
__global__ void ssd_combine_kernel(const float* __restrict__ Sloc,
                                   const float* __restrict__ cumdt,
                                   const float* __restrict__ A_log,
                                   float* __restrict__ Sin)
{
    int bh = blockIdx.x;
    int b = bh >> 5, h = bh & 31;
    float A = -__expf(A_log[h]);
    int tid = threadIdx.x;
    int p = tid >> 2, quad = tid & 3;
    int q4 = quad * 4;

    float4 s[4];
    #pragma unroll
    for (int j4 = 0; j4 < 4; j4++) s[j4] = make_float4(0.f, 0.f, 0.f, 0.f);

    for (int c = 0; c < NCH; c++) {
        size_t base = (((size_t)(b * 512 + h * 16 + c)) * DHEAD + p) * DSTATE + q4;
        float dec = __expf(A * cumdt[(size_t)(b * SEQ + c * CHL + CHL - 1) * NHEADS + h]);
        #pragma unroll
        for (int j4 = 0; j4 < 4; j4++) {
            float4 sl = *(const float4*)(Sloc + base + j4 * 16);
            *(float4*)(Sin + base + j4 * 16) = s[j4];
            s[j4].x = fmaf(dec, s[j4].x, sl.x);
            s[j4].y = fmaf(dec, s[j4].y, sl.y);
            s[j4].z = fmaf(dec, s[j4].z, sl.z);
            s[j4].w = fmaf(dec, s[j4].w, sl.w);
        }
    }
}

// ---------------- SSD phase C: cross-chunk correction, 8-step tiles ----------
__global__ __launch_bounds__(256, 4)
void ssd_correct_kernel(const float* __restrict__ xconv,
                        const float* __restrict__ cumdt,
                        const float* __restrict__ A_log,
                        const float* __restrict__ Sin,
                        float* __restrict__ y)
{
    int bhc = blockIdx.x;
    int c = bhc & (NCH - 1);
    if (c == 0) return;
    int h = (bhc >> 4) & 31;
    int b = bhc >> 9;
    float A = -__expf(A_log[h]);
    int tid = threadIdx.x;
    int lane = tid & 31;
    int wrp  = tid >> 5;
    int p = tid >> 2, quad = tid & 3;
    int q4 = quad * 4;

    float sin[16];
    {
        const float* sp = Sin + ((size_t)bhc * DHEAD + p) * DSTATE + q4;
        #pragma unroll
        for (int j4 = 0; j4 < 4; j4++) {
            float4 v = *(const float4*)(sp + j4 * 16);
            sin[j4 * 4]     = v.x;
            sin[j4 * 4 + 1] = v.y;
            sin[j4 * 4 + 2] = v.z;
            sin[j4 * 4 + 3] = v.w;
        }
    }

    __shared__ float sC[TT][DSTATE];
    __shared__ float scum[TT];
    int tbase = b * SEQ + c * CHL;

    for (int t0 = 0; t0 < CHL; t0 += TT) {
        {
            const float* row = xconv + (size_t)(tbase + t0 + wrp) * CONVDIM + DINNER + DSTATE;
            sC[wrp][lane]      = row[lane];
            sC[wrp][lane + 32] = row[lane + 32];
        }
        if (tid < TT) scum[tid] = cumdt[(size_t)(tbase + t0 + tid) * NHEADS + h];
        __syncthreads();

        #pragma unroll
        for (int w = 0; w < TT; w++) {
            float acc = 0.f;
            #pragma unroll
            for (int j4 = 0; j4 < 4; j4++) {
                float4 cv = *(const float4*)&sC[w][q4 + j4 * 16];
                acc = fmaf(cv.x, sin[j4 * 4],     acc);
                acc = fmaf(cv.y, sin[j4 * 4 + 1], acc);
                acc = fmaf(cv.z, sin[j4 * 4 + 2], acc);
                acc = fmaf(cv.w, sin[j4 * 4 + 3], acc);
            }
            acc += __shfl_xor_sync(0xffffffffu, acc, 1);
            acc += __shfl_xor_sync(0xffffffffu, acc, 2);
            if (quad == 0) {
                float wgt = __expf(A * scum[w]);
                y[(size_t)(tbase + t0 + w) * DINNER + h * DHEAD + p] += wgt * acc;
            }
        }
        __syncthreads();
    }
}

// ---------------- gate (y * silu(z)) + rmsnorm + triplet split, float4 -------
__global__ void gate_norm_split_kernel(const float* __restrict__ zxbcdt,
                                       const float* __restrict__ y,
                                       const float* __restrict__ gw,
                                       __nv_bfloat16* __restrict__ O)
{
    int t = blockIdx.x;
    int tid = threadIdx.x;
    __shared__ float sv[DINNER];
    __shared__ float wsum[8];
    const float4* zr = (const float4*)(zxbcdt + (size_t)t * DINPROJ);
    const float4* yr = (const float4*)(y + (size_t)t * DINNER);
    float lsum = 0.f;
    #pragma unroll
    for (int it = 0; it < 2; it++) {
        int i4 = tid + it * 256;
        float4 z = zr[i4];
        float4 yv = yr[i4];
        float4 v;
        v.x = yv.x * (z.x / (1.f + __expf(-z.x)));
        v.y = yv.y * (z.y / (1.f + __expf(-z.y)));
        v.z = yv.z * (z.z / (1.f + __expf(-z.z)));
        v.w = yv.w * (z.w / (1.f + __expf(-z.w)));
        ((float4*)sv)[i4] = v;
        lsum += v.x * v.x + v.y * v.y + v.z * v.z + v.w * v.w;
    }
    int lane = tid & 31, wid = tid >> 5;
    #pragma unroll
    for (int off = 16; off > 0; off >>= 1)
        lsum += __shfl_xor_sync(0xffffffffu, lsum, off);
    if (lane == 0) wsum[wid] = lsum;
    __syncthreads();
    __shared__ float s_rs;
    if (tid == 0) {
        float tot = 0.f;
        for (int i = 0; i < 8; i++) tot += wsum[i];
        s_rs = rsqrtf(tot / (float)DINNER + EPSV);
    }
    __syncthreads();
    float rs = s_rs;
    __nv_bfloat16* obase = O + (size_t)t * (3 * DINNER);
    #pragma unroll
    for (int it = 0; it < 2; it++) {
        int i4 = tid + it * 256;
        float4 v = ((float4*)sv)[i4];
        float4 wv = ((const float4*)gw)[i4];
        float o[4] = {v.x * rs * wv.x, v.y * rs * wv.y, v.z * rs * wv.z, v.w * rs * wv.w};
        __nv_bfloat16 hi[4], lo[4];
        #pragma unroll
        for (int j = 0; j < 4; j++) {
            hi[j] = __float2bfloat16(o[j]);
            lo[j] = __float2bfloat16(o[j] - __bfloat162float(hi[j]));
        }
        __nv_bfloat16* orow = obase + i4 * 4;
        __nv_bfloat162* p0 = (__nv_bfloat162*)orow;
        __nv_bfloat162* p1 = (__nv_bfloat162*)(orow + DINNER);
        __nv_bfloat162* p2 = (__nv_bfloat162*)(orow + 2 * DINNER);
        p0[0] = __nv_bfloat162{hi[0], hi[1]};  p0[1] = __nv_bfloat162{hi[2], hi[3]};
        p1[0] = __nv_bfloat162{lo[0], lo[1]};  p1[1] = __nv_bfloat162{lo[2], lo[3]};
        p2[0] = __nv_bfloat162{hi[0], hi[1]};  p2[1] = __nv_bfloat162{hi[2], hi[3]};
    }
}

// ---------------- host orchestration ----------------
extern "C" void kernel_launch(void* const* d_in, const int* in_sizes, int n_in,
                              void* d_out, int out_size)
{
    const float* x        = (const float*)d_in[0];
    const float* in_w     = (const float*)d_in[1];
    const float* conv_w   = (const float*)d_in[2];
    const float* conv_b   = (const float*)d_in[3];
    const float* dt_bias  = (const float*)d_in[4];
    const float* A_log    = (const float*)d_in[5];
    const float* Dvec     = (const float*)d_in[6];
    const float* gnorm_w  = (const float*)d_in[7];
    const float* out_w    = (const float*)d_in[8];
    const float* rms_w    = (const float*)d_in[9];
    float* out = (float*)d_out;

    float *p_zx, *p_xc, *p_dt, *p_y, *p_sl, *p_si, *p_cd;
    __nv_bfloat16 *p_as, *p_bs;
    cudaGetSymbolAddress((void**)&p_zx, g_zxbcdt);
    cudaGetSymbolAddress((void**)&p_xc, g_xconv);
    cudaGetSymbolAddress((void**)&p_dt, g_dt);
    cudaGetSymbolAddress((void**)&p_y,  g_y);
    cudaGetSymbolAddress((void**)&p_sl, g_Sloc);
    cudaGetSymbolAddress((void**)&p_si, g_Sin);
    cudaGetSymbolAddress((void**)&p_cd, g_cumdt);
    cudaGetSymbolAddress((void**)&p_as, g_asp);
    cudaGetSymbolAddress((void**)&p_bs, g_bsp);

    cudaFuncSetAttribute(gemm_bf16_nt,
                         cudaFuncAttributeMaxDynamicSharedMemorySize, GEMM_SMEM_BYTES);

    cudaMemcpyAsync(out, x, (size_t)TTOT * DMODEL * sizeof(float),
                    cudaMemcpyDeviceToDevice);

    for (int layer = 0; layer < NLAYERS; layer++) {
        const float* lw_in   = in_w    + (size_t)layer * DINPROJ * DMODEL;
        const float* lw_cw   = conv_w  + (size_t)layer * CONVDIM * DCONV;
        const float* lw_cb   = conv_b  + (size_t)layer * CONVDIM;
        const float* lw_dtb  = dt_bias + (size_t)layer * NHEADS;
        const float* lw_Alog = A_log   + (size_t)layer * NHEADS;
        const float* lw_D    = Dvec    + (size_t)layer * NHEADS;
        const float* lw_gn   = gnorm_w + (size_t)layer * DINNER;
        const float* lw_out  = out_w   + (size_t)layer * DMODEL * DINNER;
        const float* lw_rms  = rms_w   + (size_t)layer * DMODEL;

        // 1. rmsnorm(x) -> bf16 triplet A operand
        rmsnorm_split_kernel<<<TTOT, 256>>>(out, lw_rms, p_as);

        // 2. in_proj
        split_w_kernel<<<(DINPROJ * DMODEL / 4 + 255) / 256, 256>>>(lw_in, p_bs,
                                                                    DINPROJ, DMODEL);
        {
            dim3 grid((DINPROJ + BN - 1) / BN, TTOT / BM);
            gemm_bf16_nt<<<grid, 128, GEMM_SMEM_BYTES>>>(p_as, p_bs, p_zx,
                                                         TTOT, DINPROJ, 3 * DMODEL, 0);
        }

        // 3. conv + silu (2 timesteps/thread)
        {
            int total = (TTOT / 2) * (CONVDIM / 4);
            conv_silu_kernel<<<(total + 255) / 256, 256>>>(p_zx, lw_cw, lw_cb, p_xc);
        }

        // 4. dt softplus
        dt_softplus_kernel<<<(TTOT * NHEADS + 255) / 256, 256>>>(p_zx, lw_dtb, p_dt);

        // 5. SSD: chunked 3-phase scan
        ssd_local_kernel<<<BATCH * NHEADS * NCH, 256>>>(p_xc, p_dt, lw_Alog, lw_D,
                                                        p_y, p_sl, p_cd);
        ssd_combine_kernel<<<BATCH * NHEADS, 256>>>(p_sl, p_cd, lw_Alog, p_si);
        ssd_correct_kernel<<<BATCH * NHEADS * NCH, 256>>>(p_xc, p_cd, lw_Alog, p_si, p_y);

        // 6. gate + rmsnorm -> bf16 triplet A operand
        gate_norm_split_kernel<<<TTOT, 256>>>(p_zx, p_y, lw_gn, p_as);

        // 7. out_proj with residual add
        split_w_kernel<<<(DMODEL * DINNER / 4 + 255) / 256, 256>>>(lw_out, p_bs,
                                                                   DMODEL, DINNER);
        {
            dim3 grid(DMODEL / BN, TTOT / BM);
            gemm_bf16_nt<<<grid, 128, GEMM_SMEM_BYTES>>>(p_as, p_bs, out,
                                                         TTOT, DMODEL, 3 * DINNER, 1);
        }
    }
}

// round 12
// speedup vs baseline: 1.0078x; 1.0078x over previous
#include <cuda_runtime.h>
#include <cuda_bf16.h>
#include <math.h>
#include <stdint.h>

// ---------------- problem constants ----------------
#define BATCH     2
#define SEQ       2048
#define TTOT      (BATCH*SEQ)        // 4096
#define DMODEL    1024
#define DINNER    2048
#define DHEAD     64
#define NHEADS    32
#define DSTATE    64
#define DCONV     4
#define CONVDIM   (DINNER + 2*DSTATE)            // 2176
#define DINPROJ   (2*DINNER + 2*DSTATE + NHEADS) // 4256
#define NLAYERS   4
#define EPSV      1e-5f

#define CHL       128                 // scan chunk length
#define NCH       (SEQ/CHL)           // 16 chunks per sequence
#define TT        8                   // scan timestep tile
#define NTILES    (CHL/TT)            // 16

// ---------------- scratch (device globals; no allocs allowed) ----------------
__device__ float g_zxbcdt[(size_t)TTOT * DINPROJ];
__device__ float g_xconv[(size_t)TTOT * CONVDIM];
__device__ float g_y[(size_t)TTOT * DINNER];
__device__ __nv_bfloat16 g_asp[(size_t)TTOT * 3 * DINNER];    // A triplets
__device__ __nv_bfloat16 g_bsp[(size_t)DINPROJ * 3 * DMODEL]; // B triplets
__device__ float g_Sloc[(size_t)BATCH*NHEADS*NCH * DHEAD * DSTATE];
__device__ float g_Sin [(size_t)BATCH*NHEADS*NCH * DHEAD * DSTATE];
__device__ float g_cumdt[(size_t)TTOT * NHEADS];

__device__ __forceinline__ uint32_t s2u(const void* p) {
    return (uint32_t)__cvta_generic_to_shared(p);
}

__device__ __forceinline__ float softplusf(float v) {
    return (v > 20.f) ? v : log1pf(__expf(v));
}

// =========== bf16 mma.sync NT GEMM: C[M,N] = A[M,K'] @ B[N,K']^T (+C) =======
// Triplet operands: A row = [hi|lo|hi] (3K), B row = [hi|hi|lo] (3K).
// CTA tile 128x128, 8 warps (2x4), warp tile 64x32, BK=64, 3-stage cp.async.
#define BM 128
#define BN 128
#define BK 64
#define NSTG 3
#define STG_A 16384
#define STG_BYTES (2*STG_A)
#define GEMM_SMEM_BYTES (NSTG * STG_BYTES)   // 98304 B

__device__ __forceinline__ void gemm_issue(
    const __nv_bfloat16* __restrict__ A, const __nv_bfloat16* __restrict__ B,
    int N, int K, int m0, int n0, int kbase,
    char* As, char* Bs, int tid)
{
    #pragma unroll
    for (int it = 0; it < 4; it++) {
        int id  = tid + it * 256;
        int row = id >> 3;
        int ch  = id & 7;
        int sw  = ch ^ (row & 7);
        int dst = row * 128 + sw * 16;
        {
            uint32_t saddr = s2u(As + dst);
            const void* g = A + (size_t)(m0 + row) * K + kbase + ch * 8;
            asm volatile("cp.async.cg.shared.global [%0], [%1], 16;"
                         :: "r"(saddr), "l"(g));
        }
        {
            uint32_t saddr = s2u(Bs + dst);
            int valid = (n0 + row) < N;
            const void* g = B + (valid ? ((size_t)(n0 + row) * K + kbase + ch * 8) : 0);
            int sz = valid ? 16 : 0;
            asm volatile("cp.async.cg.shared.global [%0], [%1], 16, %2;"
                         :: "r"(saddr), "l"(g), "r"(sz));
        }
    }
}

__global__ __launch_bounds__(256, 2)
void gemm_bf16_nt(const __nv_bfloat16* __restrict__ A, const __nv_bfloat16* __restrict__ B,
                  float* __restrict__ C, int M, int N, int K, int addC)
{
    extern __shared__ __align__(16) char dynsmem[];

    int tid  = threadIdx.x;
    int lane = tid & 31;
    int wid  = tid >> 5;
    int m0 = blockIdx.y * BM;
    int n0 = blockIdx.x * BN;
    int wm = (wid & 1) * 64;
    int wn = (wid >> 1) * 32;

    float acc[4][4][4];
    #pragma unroll
    for (int a = 0; a < 4; a++)
        #pragma unroll
        for (int b = 0; b < 4; b++)
            #pragma unroll
            for (int c = 0; c < 4; c++) acc[a][b][c] = 0.f;

    int NT = K / BK;

    #pragma unroll
    for (int s = 0; s < NSTG - 1; s++) {
        gemm_issue(A, B, N, K, m0, n0, s * BK,
                   dynsmem + s * STG_BYTES, dynsmem + s * STG_BYTES + STG_A, tid);
        asm volatile("cp.async.commit_group;" ::: "memory");
    }

    int sc = 0;
    int si = NSTG - 1;
    for (int kt = 0; kt < NT; kt++) {
        asm volatile("cp.async.wait_group 1;" ::: "memory");
        __syncthreads();
        if (kt + 2 < NT) {
            gemm_issue(A, B, N, K, m0, n0, (kt + 2) * BK,
                       dynsmem + si * STG_BYTES, dynsmem + si * STG_BYTES + STG_A, tid);
        }
        asm volatile("cp.async.commit_group;" ::: "memory");
        si = (si == NSTG - 1) ? 0 : si + 1;

        char* As = dynsmem + sc * STG_BYTES;
        char* Bs = As + STG_A;
        sc = (sc == NSTG - 1) ? 0 : sc + 1;

        #pragma unroll
        for (int ks = 0; ks < 4; ks++) {
            uint32_t af[4][4];
            uint32_t bf[4][2];
            #pragma unroll
            for (int mi = 0; mi < 4; mi++) {
                int row = wm + mi * 16 + (lane & 15);
                int ch  = ks * 2 + (lane >> 4);
                int sw  = ch ^ (row & 7);
                uint32_t addr = s2u(As + row * 128 + sw * 16);
                asm volatile("ldmatrix.sync.aligned.m8n8.x4.shared.b16 {%0,%1,%2,%3}, [%4];"
                             : "=r"(af[mi][0]), "=r"(af[mi][1]),
                               "=r"(af[mi][2]), "=r"(af[mi][3])
                             : "r"(addr));
            }
            #pragma unroll
            for (int nj = 0; nj < 4; nj += 2) {
                int row = wn + nj * 8 + (lane >> 4) * 8 + (lane & 7);
                int ch  = ks * 2 + ((lane >> 3) & 1);
                int sw  = ch ^ (row & 7);
                uint32_t addr = s2u(Bs + row * 128 + sw * 16);
                asm volatile("ldmatrix.sync.aligned.m8n8.x4.shared.b16 {%0,%1,%2,%3}, [%4];"
                             : "=r"(bf[nj][0]), "=r"(bf[nj][1]),
                               "=r"(bf[nj + 1][0]), "=r"(bf[nj + 1][1])
                             : "r"(addr));
            }
            #pragma unroll
            for (int mi = 0; mi < 4; mi++)
                #pragma unroll
                for (int nj = 0; nj < 4; nj++)
                    asm volatile(
                        "mma.sync.aligned.m16n8k16.row.col.f32.bf16.bf16.f32 "
                        "{%0,%1,%2,%3}, {%4,%5,%6,%7}, {%8,%9}, {%0,%1,%2,%3};"
                        : "+f"(acc[mi][nj][0]), "+f"(acc[mi][nj][1]),
                          "+f"(acc[mi][nj][2]), "+f"(acc[mi][nj][3])
                        : "r"(af[mi][0]), "r"(af[mi][1]),
                          "r"(af[mi][2]), "r"(af[mi][3]),
                          "r"(bf[nj][0]), "r"(bf[nj][1]));
        }
    }

    #pragma unroll
    for (int mi = 0; mi < 4; mi++) {
        int r0 = m0 + wm + mi * 16 + (lane >> 2);
        #pragma unroll
        for (int nj = 0; nj < 4; nj++) {
            int c0 = n0 + wn + nj * 8 + (lane & 3) * 2;
            if (c0 < N) {
                float2* p0 = (float2*)(C + (size_t)r0 * N + c0);
                float2* p1 = (float2*)(C + (size_t)(r0 + 8) * N + c0);
                float2 v0 = make_float2(acc[mi][nj][0], acc[mi][nj][1]);
                float2 v1 = make_float2(acc[mi][nj][2], acc[mi][nj][3]);
                if (addC) {
                    float2 o0 = *p0, o1 = *p1;
                    v0.x += o0.x; v0.y += o0.y;
                    v1.x += o1.x; v1.y += o1.y;
                }
                *p0 = v0;
                *p1 = v1;
            }
        }
    }
}

// ---------------- rmsnorm + bf16 triplet split ([hi,lo,hi]), float4 ---------
__global__ void rmsnorm_split_kernel(const float* __restrict__ x,
                                     const float* __restrict__ w,
                                     __nv_bfloat16* __restrict__ O)
{
    int t = blockIdx.x;
    int tid = threadIdx.x;
    const float4* xr4 = (const float4*)(x + (size_t)t * DMODEL);
    float4 v = xr4[tid];
    float lsum = v.x * v.x + v.y * v.y + v.z * v.z + v.w * v.w;

    __shared__ float wsum[8];
    int lane = tid & 31, wid = tid >> 5;
    #pragma unroll
    for (int off = 16; off > 0; off >>= 1)
        lsum += __shfl_xor_sync(0xffffffffu, lsum, off);
    if (lane == 0) wsum[wid] = lsum;
    __syncthreads();
    __shared__ float s_rs;
    if (tid == 0) {
        float tot = 0.f;
        for (int i = 0; i < 8; i++) tot += wsum[i];
        s_rs = rsqrtf(tot / (float)DMODEL + EPSV);
    }
    __syncthreads();
    float rs = s_rs;
    float4 wv = ((const float4*)w)[tid];
    float o[4] = {v.x * rs * wv.x, v.y * rs * wv.y, v.z * rs * wv.z, v.w * rs * wv.w};
    __nv_bfloat16 hi[4], lo[4];
    #pragma unroll
    for (int j = 0; j < 4; j++) {
        hi[j] = __float2bfloat16(o[j]);
        lo[j] = __float2bfloat16(o[j] - __bfloat162float(hi[j]));
    }
    __nv_bfloat16* orow = O + (size_t)t * (3 * DMODEL) + tid * 4;
    __nv_bfloat162* p0 = (__nv_bfloat162*)orow;
    __nv_bfloat162* p1 = (__nv_bfloat162*)(orow + DMODEL);
    __nv_bfloat162* p2 = (__nv_bfloat162*)(orow + 2 * DMODEL);
    p0[0] = __nv_bfloat162{hi[0], hi[1]};  p0[1] = __nv_bfloat162{hi[2], hi[3]};
    p1[0] = __nv_bfloat162{lo[0], lo[1]};  p1[1] = __nv_bfloat162{lo[2], lo[3]};
    p2[0] = __nv_bfloat162{hi[0], hi[1]};  p2[1] = __nv_bfloat162{hi[2], hi[3]};
}

// ---------------- weight split: fp32 -> [hi, hi, lo] triplet, float4 --------
__global__ void split_w_kernel(const float* __restrict__ X, __nv_bfloat16* __restrict__ O,
                               int rows, int K)
{
    int i4 = blockIdx.x * blockDim.x + threadIdx.x;
    int kq = K >> 2;
    if (i4 >= rows * kq) return;
    int r = i4 / kq;
    int k = (i4 - r * kq) * 4;
    float4 x = ((const float4*)X)[i4];
    float xv[4] = {x.x, x.y, x.z, x.w};
    __nv_bfloat16 hi[4], lo[4];
    #pragma unroll
    for (int j = 0; j < 4; j++) {
        hi[j] = __float2bfloat16(xv[j]);
        lo[j] = __float2bfloat16(xv[j] - __bfloat162float(hi[j]));
    }
    __nv_bfloat16* orow = O + (size_t)r * (3 * K) + k;
    __nv_bfloat162* p0 = (__nv_bfloat162*)orow;
    __nv_bfloat162* p1 = (__nv_bfloat162*)(orow + K);
    __nv_bfloat162* p2 = (__nv_bfloat162*)(orow + 2 * K);
    p0[0] = __nv_bfloat162{hi[0], hi[1]};  p0[1] = __nv_bfloat162{hi[2], hi[3]};
    p1[0] = __nv_bfloat162{hi[0], hi[1]};  p1[1] = __nv_bfloat162{hi[2], hi[3]};
    p2[0] = __nv_bfloat162{lo[0], lo[1]};  p2[1] = __nv_bfloat162{lo[2], lo[3]};
}

// ---------------- depthwise conv(4) + silu: 2 timesteps per thread ----------
__global__ void conv_silu_kernel(const float* __restrict__ zxbcdt,
                                 const float* __restrict__ cw,
                                 const float* __restrict__ cb,
                                 float* __restrict__ xconv)
{
    const int NC4 = CONVDIM / 4;
    int i = blockIdx.x * blockDim.x + threadIdx.x;
    if (i >= (TTOT / 2) * NC4) return;
    int c4 = i % NC4;
    int tp = i / NC4;
    int b  = tp / (SEQ / 2);
    int l0 = (tp % (SEQ / 2)) * 2;
    int ch = c4 * 4;

    float wk[DCONV][4];
    #pragma unroll
    for (int j = 0; j < 4; j++) {
        float4 w = *(const float4*)(cw + (ch + j) * DCONV);
        wk[0][j] = w.x; wk[1][j] = w.y; wk[2][j] = w.z; wk[3][j] = w.w;
    }
    float4 bb = *(const float4*)(cb + ch);

    float4 in[5];
    #pragma unroll
    for (int k = 0; k < 5; k++) {
        int ll = l0 - 3 + k;
        if (ll >= 0)
            in[k] = *(const float4*)(zxbcdt + (size_t)(b * SEQ + ll) * DINPROJ + DINNER + ch);
        else
            in[k] = make_float4(0.f, 0.f, 0.f, 0.f);
    }

    float a0[4] = {bb.x, bb.y, bb.z, bb.w};
    float a1[4] = {bb.x, bb.y, bb.z, bb.w};
    #pragma unroll
    for (int k = 0; k < DCONV; k++) {
        float* v0 = (float*)&in[k];
        float* v1 = (float*)&in[k + 1];
        #pragma unroll
        for (int j = 0; j < 4; j++) {
            a0[j] = fmaf(v0[j], wk[k][j], a0[j]);
            a1[j] = fmaf(v1[j], wk[k][j], a1[j]);
        }
    }
    float4 o0, o1;
    o0.x = a0[0] / (1.f + __expf(-a0[0]));
    o0.y = a0[1] / (1.f + __expf(-a0[1]));
    o0.z = a0[2] / (1.f + __expf(-a0[2]));
    o0.w = a0[3] / (1.f + __expf(-a0[3]));
    o1.x = a1[0] / (1.f + __expf(-a1[0]));
    o1.y = a1[1] / (1.f + __expf(-a1[1]));
    o1.z = a1[2] / (1.f + __expf(-a1[2]));
    o1.w = a1[3] / (1.f + __expf(-a1[3]));
    *(float4*)(xconv + (size_t)(b * SEQ + l0) * CONVDIM + ch)     = o0;
    *(float4*)(xconv + (size_t)(b * SEQ + l0 + 1) * CONVDIM + ch) = o1;
}

// ---------------- SSD phase A: fused dt + triple-buffered local scan --------
// thread = (p, quad); quad owns n = quad*4 + j4*16 + jj (conflict-free LDS.128).
// sBC[buf][w] = [B(64f) | C(64f)] (contiguous 512B load from xconv).
__device__ __forceinline__ void ssd_local_issue(
    const float* __restrict__ xconv, const float* __restrict__ zxbcdt,
    int tbase, int t0, int h,
    float* sBC, float* sX, float* sdtraw, int tid)
{
    {   // BC: 8 timesteps x 32 chunks of 16B
        int w = tid >> 5, ch = tid & 31;
        const void* g = xconv + (size_t)(tbase + t0 + w) * CONVDIM + DINNER + ch * 4;
        asm volatile("cp.async.cg.shared.global [%0], [%1], 16;"
                     :: "r"(s2u(sBC + w * 128 + ch * 4)), "l"(g));
    }
    if (tid < 128) {  // X: 8 timesteps x 16 chunks
        int w = tid >> 4, ch = tid & 15;
        const void* g = xconv + (size_t)(tbase + t0 + w) * CONVDIM + h * DHEAD + ch * 4;
        asm volatile("cp.async.cg.shared.global [%0], [%1], 16;"
                     :: "r"(s2u(sX + w * 64 + ch * 4)), "l"(g));
    }
    if (tid < TT) {   // raw dt scalar
        const void* g = zxbcdt + (size_t)(tbase + t0 + tid) * DINPROJ
                        + (DINPROJ - NHEADS) + h;
        asm volatile("cp.async.ca.shared.global [%0], [%1], 4;"
                     :: "r"(s2u(sdtraw + tid)), "l"(g));
    }
}

__global__ __launch_bounds__(256, 4)
void ssd_local_kernel(const float* __restrict__ xconv,
                      const float* __restrict__ zxbcdt,
                      const float* __restrict__ dt_bias,
                      const float* __restrict__ A_log,
                      const float* __restrict__ Dvec,
                      float* __restrict__ y,
                      float* __restrict__ Sloc,
                      float* __restrict__ cumdt)
{
    int bhc = blockIdx.x;
    int c = bhc & (NCH - 1);
    int h = (bhc >> 4) & 31;
    int b = bhc >> 9;
    float A    = -__expf(A_log[h]);
    float Dh   = Dvec[h];
    float bias = dt_bias[h];
    int tid  = threadIdx.x;
    int p    = tid >> 2;
    int quad = tid & 3;
    int q4   = quad * 4;

    __shared__ float sBC[3][TT][128];
    __shared__ float sX[3][TT][DHEAD];
    __shared__ float sdtraw[3][TT];

    float s[16];
    #pragma unroll
    for (int j = 0; j < 16; j++) s[j] = 0.f;
    float cum = 0.f;
    int tbase = b * SEQ + c * CHL;

    // prologue: tile 0 into buf 0
    ssd_local_issue(xconv, zxbcdt, tbase, 0, h,
                    &sBC[0][0][0], &sX[0][0][0], sdtraw[0], tid);
    asm volatile("cp.async.commit_group;" ::: "memory");

    for (int i = 0; i < NTILES; i++) {
        if (i + 1 < NTILES) {
            int nb = (i + 1) % 3;
            ssd_local_issue(xconv, zxbcdt, tbase, (i + 1) * TT, h,
                            &sBC[nb][0][0], &sX[nb][0][0], sdtraw[nb], tid);
        }
        asm volatile("cp.async.commit_group;" ::: "memory");
        asm volatile("cp.async.wait_group 1;" ::: "memory");
        __syncthreads();

        int bf = i % 3;
        if (tid == 0) {
            float cc = cum;
            #pragma unroll
            for (int w = 0; w < TT; w++) {
                cc += softplusf(sdtraw[bf][w] + bias);
                cumdt[(size_t)(tbase + i * TT + w) * NHEADS + h] = cc;
            }
            cum = cc;
        }

        #pragma unroll
        for (int w = 0; w < TT; w++) {
            float dts = softplusf(sdtraw[bf][w] + bias);
            float da  = __expf(dts * A);
            float xp  = sX[bf][w][p] * dts;
            float accv = 0.f;
            #pragma unroll
            for (int j4 = 0; j4 < 4; j4++) {
                float4 bv = *(const float4*)&sBC[bf][w][q4 + j4 * 16];
                float4 cv = *(const float4*)&sBC[bf][w][64 + q4 + j4 * 16];
                float* bvp = (float*)&bv;
                float* cvp = (float*)&cv;
                #pragma unroll
                for (int jj = 0; jj < 4; jj++) {
                    int idx = j4 * 4 + jj;
                    s[idx] = fmaf(da, s[idx], xp * bvp[jj]);
                    accv   = fmaf(cvp[jj], s[idx], accv);
                }
            }
            accv += __shfl_xor_sync(0xffffffffu, accv, 1);
            accv += __shfl_xor_sync(0xffffffffu, accv, 2);
            if (quad == 0)
                y[(size_t)(tbase + i * TT + w) * DINNER + h * DHEAD + p]
                    = accv + Dh * sX[bf][w][p];
        }
        // no trailing barrier: next issue targets buf (i+2)%3, whose last
        // reader (compute at i-1) is separated by the barrier above.
    }

    float* sl = Sloc + ((size_t)bhc * DHEAD + p) * DSTATE + q4;
    #pragma unroll
    for (int j4 = 0; j4 < 4; j4++)
        *(float4*)(sl + j4 * 16) = make_float4(s[j4 * 4], s[j4 * 4 + 1],
                                               s[j4 * 4 + 2], s[j4 * 4 + 3]);
}

// ---------------- SSD phase B: sequential carry combine over chunks ----------
__global__ void ssd_combine_kernel(const float* __restrict__ Sloc,
                                   const float* __restrict__ cumdt,
                                   const float* __restrict__ A_log,
                                   float* __restrict__ Sin)
{
    int bh = blockIdx.x;
    int b = bh >> 5, h = bh & 31;
    float A = -__expf(A_log[h]);
    int tid = threadIdx.x;
    int p = tid >> 2, quad = tid & 3;
    int q4 = quad * 4;

    float4 s[4];
    #pragma unroll
    for (int j4 = 0; j4 < 4; j4++) s[j4] = make_float4(0.f, 0.f, 0.f, 0.f);

    for (int c = 0; c < NCH; c++) {
        size_t base = (((size_t)(b * 512 + h * 16 + c)) * DHEAD + p) * DSTATE + q4;
        float dec = __expf(A * cumdt[(size_t)(b * SEQ + c * CHL + CHL - 1) * NHEADS + h]);
        #pragma unroll
        for (int j4 = 0; j4 < 4; j4++) {
            float4 sl = *(const float4*)(Sloc + base + j4 * 16);
            *(float4*)(Sin + base + j4 * 16) = s[j4];
            s[j4].x = fmaf(dec, s[j4].x, sl.x);
            s[j4].y = fmaf(dec, s[j4].y, sl.y);
            s[j4].z = fmaf(dec, s[j4].z, sl.z);
            s[j4].w = fmaf(dec, s[j4].w, sl.w);
        }
    }
}

// ---------------- SSD phase C: triple-buffered cross-chunk correction -------
__device__ __forceinline__ void ssd_corr_issue(
    const float* __restrict__ xconv, const float* __restrict__ cumdt,
    int tbase, int t0, int h, float* sC, float* scum, int tid)
{
    if (tid < 128) {  // C: 8 timesteps x 16 chunks of 16B
        int w = tid >> 4, ch = tid & 15;
        const void* g = xconv + (size_t)(tbase + t0 + w) * CONVDIM
                        + DINNER + DSTATE + ch * 4;
        asm volatile("cp.async.cg.shared.global [%0], [%1], 16;"
                     :: "r"(s2u(sC + w * 64 + ch * 4)), "l"(g));
    }
    if (tid < TT) {
        const void* g = cumdt + (size_t)(tbase + t0 + tid) * NHEADS + h;
        asm volatile("cp.async.ca.shared.global [%0], [%1], 4;"
                     :: "r"(s2u(scum + tid)), "l"(g));
    }
}

__global__ __launch_bounds__(256, 4)
void ssd_correct_kernel(const float* __restrict__ xconv,
                        const float* __restrict__ cumdt,
                        const float* __restrict__ A_log,
                        const float* __restrict__ Sin,
                        float* __restrict__ y)
{
    int bhc = blockIdx.x;
    int c = bhc & (NCH - 1);
    if (c == 0) return;
    int h = (bhc >> 4) & 31;
    int b = bhc >> 9;
    float A = -__expf(A_log[h]);
    int tid = threadIdx.x;
    int p = tid >> 2, quad = tid & 3;
    int q4 = quad * 4;

    float sin[16];
    {
        const float* sp = Sin + ((size_t)bhc * DHEAD + p) * DSTATE + q4;
        #pragma unroll
        for (int j4 = 0; j4 < 4; j4++) {
            float4 v = *(const float4*)(sp + j4 * 16);
            sin[j4 * 4]     = v.x;
            sin[j4 * 4 + 1] = v.y;
            sin[j4 * 4 + 2] = v.z;
            sin[j4 * 4 + 3] = v.w;
        }
    }

    __shared__ float sC[3][TT][DSTATE];
    __shared__ float scum[3][TT];
    int tbase = b * SEQ + c * CHL;

    ssd_corr_issue(xconv, cumdt, tbase, 0, h, &sC[0][0][0], scum[0], tid);
    asm volatile("cp.async.commit_group;" ::: "memory");

    for (int i = 0; i < NTILES; i++) {
        if (i + 1 < NTILES) {
            int nb = (i + 1) % 3;
            ssd_corr_issue(xconv, cumdt, tbase, (i + 1) * TT, h,
                           &sC[nb][0][0], scum[nb], tid);
        }
        asm volatile("cp.async.commit_group;" ::: "memory");
        asm volatile("cp.async.wait_group 1;" ::: "memory");
        __syncthreads();

        int bf = i % 3;
        #pragma unroll
        for (int w = 0; w < TT; w++) {
            float acc = 0.f;
            #pragma unroll
            for (int j4 = 0; j4 < 4; j4++) {
                float4 cv = *(const float4*)&sC[bf][w][q4 + j4 * 16];
                acc = fmaf(cv.x, sin[j4 * 4],     acc);
                acc = fmaf(cv.y, sin[j4 * 4 + 1], acc);
                acc = fmaf(cv.z, sin[j4 * 4 + 2], acc);
                acc = fmaf(cv.w, sin[j4 * 4 + 3], acc);
            }
            acc += __shfl_xor_sync(0xffffffffu, acc, 1);
            acc += __shfl_xor_sync(0xffffffffu, acc, 2);
            if (quad == 0) {
                float wgt = __expf(A * scum[bf][w]);
                y[(size_t)(tbase + i * TT + w) * DINNER + h * DHEAD + p] += wgt * acc;
            }
        }
    }
}

// ---------------- gate (y * silu(z)) + rmsnorm + triplet split, float4 -------
__global__ void gate_norm_split_kernel(const float* __restrict__ zxbcdt,
                                       const float* __restrict__ y,
                                       const float* __restrict__ gw,
                                       __nv_bfloat16* __restrict__ O)
{
    int t = blockIdx.x;
    int tid = threadIdx.x;
    __shared__ float sv[DINNER];
    __shared__ float wsum[8];
    const float4* zr = (const float4*)(zxbcdt + (size_t)t * DINPROJ);
    const float4* yr = (const float4*)(y + (size_t)t * DINNER);
    float lsum = 0.f;
    #pragma unroll
    for (int it = 0; it < 2; it++) {
        int i4 = tid + it * 256;
        float4 z = zr[i4];
        float4 yv = yr[i4];
        float4 v;
        v.x = yv.x * (z.x / (1.f + __expf(-z.x)));
        v.y = yv.y * (z.y / (1.f + __expf(-z.y)));
        v.z = yv.z * (z.z / (1.f + __expf(-z.z)));
        v.w = yv.w * (z.w / (1.f + __expf(-z.w)));
        ((float4*)sv)[i4] = v;
        lsum += v.x * v.x + v.y * v.y + v.z * v.z + v.w * v.w;
    }
    int lane = tid & 31, wid = tid >> 5;
    #pragma unroll
    for (int off = 16; off > 0; off >>= 1)
        lsum += __shfl_xor_sync(0xffffffffu, lsum, off);
    if (lane == 0) wsum[wid] = lsum;
    __syncthreads();
    __shared__ float s_rs;
    if (tid == 0) {
        float tot = 0.f;
        for (int i = 0; i < 8; i++) tot += wsum[i];
        s_rs = rsqrtf(tot / (float)DINNER + EPSV);
    }
    __syncthreads();
    float rs = s_rs;
    __nv_bfloat16* obase = O + (size_t)t * (3 * DINNER);
    #pragma unroll
    for (int it = 0; it < 2; it++) {
        int i4 = tid + it * 256;
        float4 v = ((float4*)sv)[i4];
        float4 wv = ((const float4*)gw)[i4];
        float o[4] = {v.x * rs * wv.x, v.y * rs * wv.y, v.z * rs * wv.z, v.w * rs * wv.w};
        __nv_bfloat16 hi[4], lo[4];
        #pragma unroll
        for (int j = 0; j < 4; j++) {
            hi[j] = __float2bfloat16(o[j]);
            lo[j] = __float2bfloat16(o[j] - __bfloat162float(hi[j]));
        }
        __nv_bfloat16* orow = obase + i4 * 4;
        __nv_bfloat162* p0 = (__nv_bfloat162*)orow;
        __nv_bfloat162* p1 = (__nv_bfloat162*)(orow + DINNER);
        __nv_bfloat162* p2 = (__nv_bfloat162*)(orow + 2 * DINNER);
        p0[0] = __nv_bfloat162{hi[0], hi[1]};  p0[1] = __nv_bfloat162{hi[2], hi[3]};
        p1[0] = __nv_bfloat162{lo[0], lo[1]};  p1[1] = __nv_bfloat162{lo[2], lo[3]};
        p2[0] = __nv_bfloat162{hi[0], hi[1]};  p2[1] = __nv_bfloat162{hi[2], hi[3]};
    }
}

// ---------------- host orchestration ----------------
extern "C" void kernel_launch(void* const* d_in, const int* in_sizes, int n_in,
                              void* d_out, int out_size)
{
    const float* x        = (const float*)d_in[0];
    const float* in_w     = (const float*)d_in[1];
    const float* conv_w   = (const float*)d_in[2];
    const float* conv_b   = (const float*)d_in[3];
    const float* dt_bias  = (const float*)d_in[4];
    const float* A_log    = (const float*)d_in[5];
    const float* Dvec     = (const float*)d_in[6];
    const float* gnorm_w  = (const float*)d_in[7];
    const float* out_w    = (const float*)d_in[8];
    const float* rms_w    = (const float*)d_in[9];
    float* out = (float*)d_out;

    float *p_zx, *p_xc, *p_y, *p_sl, *p_si, *p_cd;
    __nv_bfloat16 *p_as, *p_bs;
    cudaGetSymbolAddress((void**)&p_zx, g_zxbcdt);
    cudaGetSymbolAddress((void**)&p_xc, g_xconv);
    cudaGetSymbolAddress((void**)&p_y,  g_y);
    cudaGetSymbolAddress((void**)&p_sl, g_Sloc);
    cudaGetSymbolAddress((void**)&p_si, g_Sin);
    cudaGetSymbolAddress((void**)&p_cd, g_cumdt);
    cudaGetSymbolAddress((void**)&p_as, g_asp);
    cudaGetSymbolAddress((void**)&p_bs, g_bsp);

    cudaFuncSetAttribute(gemm_bf16_nt,
                         cudaFuncAttributeMaxDynamicSharedMemorySize, GEMM_SMEM_BYTES);

    cudaMemcpyAsync(out, x, (size_t)TTOT * DMODEL * sizeof(float),
                    cudaMemcpyDeviceToDevice);

    for (int layer = 0; layer < NLAYERS; layer++) {
        const float* lw_in   = in_w    + (size_t)layer * DINPROJ * DMODEL;
        const float* lw_cw   = conv_w  + (size_t)layer * CONVDIM * DCONV;
        const float* lw_cb   = conv_b  + (size_t)layer * CONVDIM;
        const float* lw_dtb  = dt_bias + (size_t)layer * NHEADS;
        const float* lw_Alog = A_log   + (size_t)layer * NHEADS;
        const float* lw_D    = Dvec    + (size_t)layer * NHEADS;
        const float* lw_gn   = gnorm_w + (size_t)layer * DINNER;
        const float* lw_out  = out_w   + (size_t)layer * DMODEL * DINNER;
        const float* lw_rms  = rms_w   + (size_t)layer * DMODEL;

        // 1. rmsnorm(x) -> bf16 triplet A operand
        rmsnorm_split_kernel<<<TTOT, 256>>>(out, lw_rms, p_as);

        // 2. in_proj
        split_w_kernel<<<(DINPROJ * DMODEL / 4 + 255) / 256, 256>>>(lw_in, p_bs,
                                                                    DINPROJ, DMODEL);
        {
            dim3 grid((DINPROJ + BN - 1) / BN, TTOT / BM);
            gemm_bf16_nt<<<grid, 256, GEMM_SMEM_BYTES>>>(p_as, p_bs, p_zx,
                                                         TTOT, DINPROJ, 3 * DMODEL, 0);
        }

        // 3. conv + silu (2 timesteps/thread)
        {
            int total = (TTOT / 2) * (CONVDIM / 4);
            conv_silu_kernel<<<(total + 255) / 256, 256>>>(p_zx, lw_cw, lw_cb, p_xc);
        }

        // 4. SSD: fused-dt chunked 3-phase scan
        ssd_local_kernel<<<BATCH * NHEADS * NCH, 256>>>(p_xc, p_zx, lw_dtb,
                                                        lw_Alog, lw_D,
                                                        p_y, p_sl, p_cd);
        ssd_combine_kernel<<<BATCH * NHEADS, 256>>>(p_sl, p_cd, lw_Alog, p_si);
        ssd_correct_kernel<<<BATCH * NHEADS * NCH, 256>>>(p_xc, p_cd, lw_Alog, p_si, p_y);

        // 5. gate + rmsnorm -> bf16 triplet A operand
        gate_norm_split_kernel<<<TTOT, 256>>>(p_zx, p_y, lw_gn, p_as);

        // 6. out_proj with residual add
        split_w_kernel<<<(DMODEL * DINNER / 4 + 255) / 256, 256>>>(lw_out, p_bs,
                                                                   DMODEL, DINNER);
        {
            dim3 grid(DMODEL / BN, TTOT / BM);
            gemm_bf16_nt<<<grid, 256, GEMM_SMEM_BYTES>>>(p_as, p_bs, out,
                                                         TTOT, DMODEL, 3 * DINNER, 1);
        }
    }
}

// round 13
// speedup vs baseline: 1.0130x; 1.0052x over previous
#include <cuda_runtime.h>
#include <cuda_bf16.h>
#include <math.h>
#include <stdint.h>

// ---------------- problem constants ----------------
#define BATCH     2
#define SEQ       2048
#define TTOT      (BATCH*SEQ)        // 4096
#define DMODEL    1024
#define DINNER    2048
#define DHEAD     64
#define NHEADS    32
#define DSTATE    64
#define DCONV     4
#define CONVDIM   (DINNER + 2*DSTATE)            // 2176
#define DINPROJ   (2*DINNER + 2*DSTATE + NHEADS) // 4256
#define NLAYERS   4
#define EPSV      1e-5f

#define CHL       128                 // scan chunk length
#define NCH       (SEQ/CHL)           // 16 chunks per sequence
#define TT        8                   // scan timestep tile
#define NTILES    (CHL/TT)            // 16

// ---------------- scratch (device globals; no allocs allowed) ----------------
__device__ float g_zxbcdt[(size_t)TTOT * DINPROJ];
__device__ float g_xconv[(size_t)TTOT * CONVDIM];
__device__ float g_y[(size_t)TTOT * DINNER];
__device__ __nv_bfloat16 g_asp[(size_t)TTOT * 3 * DINNER];    // activation triplets
// per-layer weight triplets (computed once per call, outside the layer loop)
__device__ __nv_bfloat16 g_bw_in [(size_t)NLAYERS * DINPROJ * 3 * DMODEL];
__device__ __nv_bfloat16 g_bw_out[(size_t)NLAYERS * DMODEL * 3 * DINNER];
__device__ float g_Sloc[(size_t)BATCH*NHEADS*NCH * DHEAD * DSTATE];
__device__ float g_Sin [(size_t)BATCH*NHEADS*NCH * DHEAD * DSTATE];
__device__ float g_cumdt[(size_t)TTOT * NHEADS];

__device__ __forceinline__ uint32_t s2u(const void* p) {
    return (uint32_t)__cvta_generic_to_shared(p);
}

__device__ __forceinline__ float softplusf(float v) {
    return (v > 20.f) ? v : log1pf(__expf(v));
}

// =========== bf16 mma.sync NT GEMM: C[M,N] = A[M,K'] @ B[N,K']^T (+C) =======
// Triplet operands: A row = [hi|lo|hi] (3K), B row = [hi|hi|lo] (3K).
// CTA tile 128x128, 8 warps (2x4), warp tile 64x32, BK=64, 3-stage cp.async.
#define BM 128
#define BN 128
#define BK 64
#define NSTG 3
#define STG_A 16384
#define STG_BYTES (2*STG_A)
#define GEMM_SMEM_BYTES (NSTG * STG_BYTES)   // 98304 B

__device__ __forceinline__ void gemm_issue(
    const __nv_bfloat16* __restrict__ A, const __nv_bfloat16* __restrict__ B,
    int N, int K, int m0, int n0, int kbase,
    char* As, char* Bs, int tid)
{
    #pragma unroll
    for (int it = 0; it < 4; it++) {
        int id  = tid + it * 256;
        int row = id >> 3;
        int ch  = id & 7;
        int sw  = ch ^ (row & 7);
        int dst = row * 128 + sw * 16;
        {
            uint32_t saddr = s2u(As + dst);
            const void* g = A + (size_t)(m0 + row) * K + kbase + ch * 8;
            asm volatile("cp.async.cg.shared.global [%0], [%1], 16;"
                         :: "r"(saddr), "l"(g));
        }
        {
            uint32_t saddr = s2u(Bs + dst);
            int valid = (n0 + row) < N;
            const void* g = B + (valid ? ((size_t)(n0 + row) * K + kbase + ch * 8) : 0);
            int sz = valid ? 16 : 0;
            asm volatile("cp.async.cg.shared.global [%0], [%1], 16, %2;"
                         :: "r"(saddr), "l"(g), "r"(sz));
        }
    }
}

__global__ __launch_bounds__(256, 2)
void gemm_bf16_nt(const __nv_bfloat16* __restrict__ A, const __nv_bfloat16* __restrict__ B,
                  float* __restrict__ C, int M, int N, int K, int addC)
{
    extern __shared__ __align__(16) char dynsmem[];

    int tid  = threadIdx.x;
    int lane = tid & 31;
    int wid  = tid >> 5;
    int m0 = blockIdx.y * BM;
    int n0 = blockIdx.x * BN;
    int wm = (wid & 1) * 64;
    int wn = (wid >> 1) * 32;

    float acc[4][4][4];
    #pragma unroll
    for (int a = 0; a < 4; a++)
        #pragma unroll
        for (int b = 0; b < 4; b++)
            #pragma unroll
            for (int c = 0; c < 4; c++) acc[a][b][c] = 0.f;

    int NT = K / BK;

    #pragma unroll
    for (int s = 0; s < NSTG - 1; s++) {
        gemm_issue(A, B, N, K, m0, n0, s * BK,
                   dynsmem + s * STG_BYTES, dynsmem + s * STG_BYTES + STG_A, tid);
        asm volatile("cp.async.commit_group;" ::: "memory");
    }

    int sc = 0;
    int si = NSTG - 1;
    for (int kt = 0; kt < NT; kt++) {
        asm volatile("cp.async.wait_group 1;" ::: "memory");
        __syncthreads();
        if (kt + 2 < NT) {
            gemm_issue(A, B, N, K, m0, n0, (kt + 2) * BK,
                       dynsmem + si * STG_BYTES, dynsmem + si * STG_BYTES + STG_A, tid);
        }
        asm volatile("cp.async.commit_group;" ::: "memory");
        si = (si == NSTG - 1) ? 0 : si + 1;

        char* As = dynsmem + sc * STG_BYTES;
        char* Bs = As + STG_A;
        sc = (sc == NSTG - 1) ? 0 : sc + 1;

        #pragma unroll
        for (int ks = 0; ks < 4; ks++) {
            uint32_t af[4][4];
            uint32_t bf[4][2];
            #pragma unroll
            for (int mi = 0; mi < 4; mi++) {
                int row = wm + mi * 16 + (lane & 15);
                int ch  = ks * 2 + (lane >> 4);
                int sw  = ch ^ (row & 7);
                uint32_t addr = s2u(As + row * 128 + sw * 16);
                asm volatile("ldmatrix.sync.aligned.m8n8.x4.shared.b16 {%0,%1,%2,%3}, [%4];"
                             : "=r"(af[mi][0]), "=r"(af[mi][1]),
                               "=r"(af[mi][2]), "=r"(af[mi][3])
                             : "r"(addr));
            }
            #pragma unroll
            for (int nj = 0; nj < 4; nj += 2) {
                int row = wn + nj * 8 + (lane >> 4) * 8 + (lane & 7);
                int ch  = ks * 2 + ((lane >> 3) & 1);
                int sw  = ch ^ (row & 7);
                uint32_t addr = s2u(Bs + row * 128 + sw * 16);
                asm volatile("ldmatrix.sync.aligned.m8n8.x4.shared.b16 {%0,%1,%2,%3}, [%4];"
                             : "=r"(bf[nj][0]), "=r"(bf[nj][1]),
                               "=r"(bf[nj + 1][0]), "=r"(bf[nj + 1][1])
                             : "r"(addr));
            }
            #pragma unroll
            for (int mi = 0; mi < 4; mi++)
                #pragma unroll
                for (int nj = 0; nj < 4; nj++)
                    asm volatile(
                        "mma.sync.aligned.m16n8k16.row.col.f32.bf16.bf16.f32 "
                        "{%0,%1,%2,%3}, {%4,%5,%6,%7}, {%8,%9}, {%0,%1,%2,%3};"
                        : "+f"(acc[mi][nj][0]), "+f"(acc[mi][nj][1]),
                          "+f"(acc[mi][nj][2]), "+f"(acc[mi][nj][3])
                        : "r"(af[mi][0]), "r"(af[mi][1]),
                          "r"(af[mi][2]), "r"(af[mi][3]),
                          "r"(bf[nj][0]), "r"(bf[nj][1]));
        }
    }

    #pragma unroll
    for (int mi = 0; mi < 4; mi++) {
        int r0 = m0 + wm + mi * 16 + (lane >> 2);
        #pragma unroll
        for (int nj = 0; nj < 4; nj++) {
            int c0 = n0 + wn + nj * 8 + (lane & 3) * 2;
            if (c0 < N) {
                float2* p0 = (float2*)(C + (size_t)r0 * N + c0);
                float2* p1 = (float2*)(C + (size_t)(r0 + 8) * N + c0);
                float2 v0 = make_float2(acc[mi][nj][0], acc[mi][nj][1]);
                float2 v1 = make_float2(acc[mi][nj][2], acc[mi][nj][3]);
                if (addC) {
                    float2 o0 = *p0, o1 = *p1;
                    v0.x += o0.x; v0.y += o0.y;
                    v1.x += o1.x; v1.y += o1.y;
                }
                *p0 = v0;
                *p1 = v1;
            }
        }
    }
}

// ---------------- rmsnorm + bf16 triplet split ([hi,lo,hi]), float4 ---------
__global__ void rmsnorm_split_kernel(const float* __restrict__ x,
                                     const float* __restrict__ w,
                                     __nv_bfloat16* __restrict__ O)
{
    int t = blockIdx.x;
    int tid = threadIdx.x;
    const float4* xr4 = (const float4*)(x + (size_t)t * DMODEL);
    float4 v = xr4[tid];
    float lsum = v.x * v.x + v.y * v.y + v.z * v.z + v.w * v.w;

    __shared__ float wsum[8];
    int lane = tid & 31, wid = tid >> 5;
    #pragma unroll
    for (int off = 16; off > 0; off >>= 1)
        lsum += __shfl_xor_sync(0xffffffffu, lsum, off);
    if (lane == 0) wsum[wid] = lsum;
    __syncthreads();
    __shared__ float s_rs;
    if (tid == 0) {
        float tot = 0.f;
        for (int i = 0; i < 8; i++) tot += wsum[i];
        s_rs = rsqrtf(tot / (float)DMODEL + EPSV);
    }
    __syncthreads();
    float rs = s_rs;
    float4 wv = ((const float4*)w)[tid];
    float o[4] = {v.x * rs * wv.x, v.y * rs * wv.y, v.z * rs * wv.z, v.w * rs * wv.w};
    __nv_bfloat16 hi[4], lo[4];
    #pragma unroll
    for (int j = 0; j < 4; j++) {
        hi[j] = __float2bfloat16(o[j]);
        lo[j] = __float2bfloat16(o[j] - __bfloat162float(hi[j]));
    }
    __nv_bfloat16* orow = O + (size_t)t * (3 * DMODEL) + tid * 4;
    __nv_bfloat162* p0 = (__nv_bfloat162*)orow;
    __nv_bfloat162* p1 = (__nv_bfloat162*)(orow + DMODEL);
    __nv_bfloat162* p2 = (__nv_bfloat162*)(orow + 2 * DMODEL);
    p0[0] = __nv_bfloat162{hi[0], hi[1]};  p0[1] = __nv_bfloat162{hi[2], hi[3]};
    p1[0] = __nv_bfloat162{lo[0], lo[1]};  p1[1] = __nv_bfloat162{lo[2], lo[3]};
    p2[0] = __nv_bfloat162{hi[0], hi[1]};  p2[1] = __nv_bfloat162{hi[2], hi[3]};
}

// ---------------- weight split: fp32 -> [hi, hi, lo] triplet, float4 --------
// rows can fold the layer dimension (weights are layer-contiguous).
__global__ void split_w_kernel(const float* __restrict__ X, __nv_bfloat16* __restrict__ O,
                               int rows, int K)
{
    int i4 = blockIdx.x * blockDim.x + threadIdx.x;
    int kq = K >> 2;
    if (i4 >= rows * kq) return;
    int r = i4 / kq;
    int k = (i4 - r * kq) * 4;
    float4 x = ((const float4*)X)[i4];
    float xv[4] = {x.x, x.y, x.z, x.w};
    __nv_bfloat16 hi[4], lo[4];
    #pragma unroll
    for (int j = 0; j < 4; j++) {
        hi[j] = __float2bfloat16(xv[j]);
        lo[j] = __float2bfloat16(xv[j] - __bfloat162float(hi[j]));
    }
    __nv_bfloat16* orow = O + (size_t)r * (3 * K) + k;
    __nv_bfloat162* p0 = (__nv_bfloat162*)orow;
    __nv_bfloat162* p1 = (__nv_bfloat162*)(orow + K);
    __nv_bfloat162* p2 = (__nv_bfloat162*)(orow + 2 * K);
    p0[0] = __nv_bfloat162{hi[0], hi[1]};  p0[1] = __nv_bfloat162{hi[2], hi[3]};
    p1[0] = __nv_bfloat162{hi[0], hi[1]};  p1[1] = __nv_bfloat162{hi[2], hi[3]};
    p2[0] = __nv_bfloat162{lo[0], lo[1]};  p2[1] = __nv_bfloat162{lo[2], lo[3]};
}

// ---------------- depthwise conv(4) + silu: 4 timesteps per thread ----------
__global__ void conv_silu_kernel(const float* __restrict__ zxbcdt,
                                 const float* __restrict__ cw,
                                 const float* __restrict__ cb,
                                 float* __restrict__ xconv)
{
    const int NC4 = CONVDIM / 4;
    int i = blockIdx.x * blockDim.x + threadIdx.x;
    if (i >= (TTOT / 4) * NC4) return;
    int c4 = i % NC4;
    int tp = i / NC4;
    int b  = tp / (SEQ / 4);
    int l0 = (tp % (SEQ / 4)) * 4;
    int ch = c4 * 4;

    float wk[DCONV][4];
    #pragma unroll
    for (int j = 0; j < 4; j++) {
        float4 w = *(const float4*)(cw + (ch + j) * DCONV);
        wk[0][j] = w.x; wk[1][j] = w.y; wk[2][j] = w.z; wk[3][j] = w.w;
    }
    float4 bb = *(const float4*)(cb + ch);

    // input rows l0-3 .. l0+3 (7 rows), zero-padded below 0
    float4 in[7];
    #pragma unroll
    for (int k = 0; k < 7; k++) {
        int ll = l0 - 3 + k;
        if (ll >= 0)
            in[k] = *(const float4*)(zxbcdt + (size_t)(b * SEQ + ll) * DINPROJ + DINNER + ch);
        else
            in[k] = make_float4(0.f, 0.f, 0.f, 0.f);
    }

    #pragma unroll
    for (int o = 0; o < 4; o++) {
        float a[4] = {bb.x, bb.y, bb.z, bb.w};
        #pragma unroll
        for (int k = 0; k < DCONV; k++) {
            float* vp = (float*)&in[o + k];
            #pragma unroll
            for (int j = 0; j < 4; j++)
                a[j] = fmaf(vp[j], wk[k][j], a[j]);
        }
        float4 ov;
        ov.x = a[0] / (1.f + __expf(-a[0]));
        ov.y = a[1] / (1.f + __expf(-a[1]));
        ov.z = a[2] / (1.f + __expf(-a[2]));
        ov.w = a[3] / (1.f + __expf(-a[3]));
        *(float4*)(xconv + (size_t)(b * SEQ + l0 + o) * CONVDIM + ch) = ov;
    }
}

// ---------------- SSD phase A: fused dt + triple-buffered local scan --------
__device__ __forceinline__ void ssd_local_issue(
    const float* __restrict__ xconv, const float* __restrict__ zxbcdt,
    int tbase, int t0, int h,
    float* sBC, float* sX, float* sdtraw, int tid)
{
    {   // BC: 8 timesteps x 32 chunks of 16B
        int w = tid >> 5, ch = tid & 31;
        const void* g = xconv + (size_t)(tbase + t0 + w) * CONVDIM + DINNER + ch * 4;
        asm volatile("cp.async.cg.shared.global [%0], [%1], 16;"
                     :: "r"(s2u(sBC + w * 128 + ch * 4)), "l"(g));
    }
    if (tid < 128) {  // X: 8 timesteps x 16 chunks
        int w = tid >> 4, ch = tid & 15;
        const void* g = xconv + (size_t)(tbase + t0 + w) * CONVDIM + h * DHEAD + ch * 4;
        asm volatile("cp.async.cg.shared.global [%0], [%1], 16;"
                     :: "r"(s2u(sX + w * 64 + ch * 4)), "l"(g));
    }
    if (tid < TT) {   // raw dt scalar
        const void* g = zxbcdt + (size_t)(tbase + t0 + tid) * DINPROJ
                        + (DINPROJ - NHEADS) + h;
        asm volatile("cp.async.ca.shared.global [%0], [%1], 4;"
                     :: "r"(s2u(sdtraw + tid)), "l"(g));
    }
}

__global__ __launch_bounds__(256, 4)
void ssd_local_kernel(const float* __restrict__ xconv,
                      const float* __restrict__ zxbcdt,
                      const float* __restrict__ dt_bias,
                      const float* __restrict__ A_log,
                      const float* __restrict__ Dvec,
                      float* __restrict__ y,
                      float* __restrict__ Sloc,
                      float* __restrict__ cumdt)
{
    int bhc = blockIdx.x;
    int c = bhc & (NCH - 1);
    int h = (bhc >> 4) & 31;
    int b = bhc >> 9;
    float A    = -__expf(A_log[h]);
    float Dh   = Dvec[h];
    float bias = dt_bias[h];
    int tid  = threadIdx.x;
    int p    = tid >> 2;
    int quad = tid & 3;
    int q4   = quad * 4;

    __shared__ float sBC[3][TT][128];
    __shared__ float sX[3][TT][DHEAD];
    __shared__ float sdtraw[3][TT];

    float s[16];
    #pragma unroll
    for (int j = 0; j < 16; j++) s[j] = 0.f;
    float cum = 0.f;
    int tbase = b * SEQ + c * CHL;

    ssd_local_issue(xconv, zxbcdt, tbase, 0, h,
                    &sBC[0][0][0], &sX[0][0][0], sdtraw[0], tid);
    asm volatile("cp.async.commit_group;" ::: "memory");

    for (int i = 0; i < NTILES; i++) {
        if (i + 1 < NTILES) {
            int nb = (i + 1) % 3;
            ssd_local_issue(xconv, zxbcdt, tbase, (i + 1) * TT, h,
                            &sBC[nb][0][0], &sX[nb][0][0], sdtraw[nb], tid);
        }
        asm volatile("cp.async.commit_group;" ::: "memory");
        asm volatile("cp.async.wait_group 1;" ::: "memory");
        __syncthreads();

        int bf = i % 3;
        if (tid == 0) {
            float cc = cum;
            #pragma unroll
            for (int w = 0; w < TT; w++) {
                cc += softplusf(sdtraw[bf][w] + bias);
                cumdt[(size_t)(tbase + i * TT + w) * NHEADS + h] = cc;
            }
            cum = cc;
        }

        #pragma unroll
        for (int w = 0; w < TT; w++) {
            float dts = softplusf(sdtraw[bf][w] + bias);
            float da  = __expf(dts * A);
            float xp  = sX[bf][w][p] * dts;
            float accv = 0.f;
            #pragma unroll
            for (int j4 = 0; j4 < 4; j4++) {
                float4 bv = *(const float4*)&sBC[bf][w][q4 + j4 * 16];
                float4 cv = *(const float4*)&sBC[bf][w][64 + q4 + j4 * 16];
                float* bvp = (float*)&bv;
                float* cvp = (float*)&cv;
                #pragma unroll
                for (int jj = 0; jj < 4; jj++) {
                    int idx = j4 * 4 + jj;
                    s[idx] = fmaf(da, s[idx], xp * bvp[jj]);
                    accv   = fmaf(cvp[jj], s[idx], accv);
                }
            }
            accv += __shfl_xor_sync(0xffffffffu, accv, 1);
            accv += __shfl_xor_sync(0xffffffffu, accv, 2);
            if (quad == 0)
                y[(size_t)(tbase + i * TT + w) * DINNER + h * DHEAD + p]
                    = accv + Dh * sX[bf][w][p];
        }
    }

    float* sl = Sloc + ((size_t)bhc * DHEAD + p) * DSTATE + q4;
    #pragma unroll
    for (int j4 = 0; j4 < 4; j4++)
        *(float4*)(sl + j4 * 16) = make_float4(s[j4 * 4], s[j4 * 4 + 1],
                                               s[j4 * 4 + 2], s[j4 * 4 + 3]);
}

// ---------------- SSD phase B: sequential carry combine over chunks ----------
__global__ void ssd_combine_kernel(const float* __restrict__ Sloc,
                                   const float* __restrict__ cumdt,
                                   const float* __restrict__ A_log,
                                   float* __restrict__ Sin)
{
    int bh = blockIdx.x;
    int b = bh >> 5, h = bh & 31;
    float A = -__expf(A_log[h]);
    int tid = threadIdx.x;
    int p = tid >> 2, quad = tid & 3;
    int q4 = quad * 4;

    float4 s[4];
    #pragma unroll
    for (int j4 = 0; j4 < 4; j4++) s[j4] = make_float4(0.f, 0.f, 0.f, 0.f);

    for (int c = 0; c < NCH; c++) {
        size_t base = (((size_t)(b * 512 + h * 16 + c)) * DHEAD + p) * DSTATE + q4;
        float dec = __expf(A * cumdt[(size_t)(b * SEQ + c * CHL + CHL - 1) * NHEADS + h]);
        #pragma unroll
        for (int j4 = 0; j4 < 4; j4++) {
            float4 sl = *(const float4*)(Sloc + base + j4 * 16);
            *(float4*)(Sin + base + j4 * 16) = s[j4];
            s[j4].x = fmaf(dec, s[j4].x, sl.x);
            s[j4].y = fmaf(dec, s[j4].y, sl.y);
            s[j4].z = fmaf(dec, s[j4].z, sl.z);
            s[j4].w = fmaf(dec, s[j4].w, sl.w);
        }
    }
}

// ---------------- SSD phase C: triple-buffered cross-chunk correction -------
__device__ __forceinline__ void ssd_corr_issue(
    const float* __restrict__ xconv, const float* __restrict__ cumdt,
    int tbase, int t0, int h, float* sC, float* scum, int tid)
{
    if (tid < 128) {
        int w = tid >> 4, ch = tid & 15;
        const void* g = xconv + (size_t)(tbase + t0 + w) * CONVDIM
                        + DINNER + DSTATE + ch * 4;
        asm volatile("cp.async.cg.shared.global [%0], [%1], 16;"
                     :: "r"(s2u(sC + w * 64 + ch * 4)), "l"(g));
    }
    if (tid < TT) {
        const void* g = cumdt + (size_t)(tbase + t0 + tid) * NHEADS + h;
        asm volatile("cp.async.ca.shared.global [%0], [%1], 4;"
                     :: "r"(s2u(scum + tid)), "l"(g));
    }
}

__global__ __launch_bounds__(256, 4)
void ssd_correct_kernel(const float* __restrict__ xconv,
                        const float* __restrict__ cumdt,
                        const float* __restrict__ A_log,
                        const float* __restrict__ Sin,
                        float* __restrict__ y)
{
    int bhc = blockIdx.x;
    int c = bhc & (NCH - 1);
    if (c == 0) return;
    int h = (bhc >> 4) & 31;
    int b = bhc >> 9;
    float A = -__expf(A_log[h]);
    int tid = threadIdx.x;
    int p = tid >> 2, quad = tid & 3;
    int q4 = quad * 4;

    float sin[16];
    {
        const float* sp = Sin + ((size_t)bhc * DHEAD + p) * DSTATE + q4;
        #pragma unroll
        for (int j4 = 0; j4 < 4; j4++) {
            float4 v = *(const float4*)(sp + j4 * 16);
            sin[j4 * 4]     = v.x;
            sin[j4 * 4 + 1] = v.y;
            sin[j4 * 4 + 2] = v.z;
            sin[j4 * 4 + 3] = v.w;
        }
    }

    __shared__ float sC[3][TT][DSTATE];
    __shared__ float scum[3][TT];
    int tbase = b * SEQ + c * CHL;

    ssd_corr_issue(xconv, cumdt, tbase, 0, h, &sC[0][0][0], scum[0], tid);
    asm volatile("cp.async.commit_group;" ::: "memory");

    for (int i = 0; i < NTILES; i++) {
        if (i + 1 < NTILES) {
            int nb = (i + 1) % 3;
            ssd_corr_issue(xconv, cumdt, tbase, (i + 1) * TT, h,
                           &sC[nb][0][0], scum[nb], tid);
        }
        asm volatile("cp.async.commit_group;" ::: "memory");
        asm volatile("cp.async.wait_group 1;" ::: "memory");
        __syncthreads();

        int bf = i % 3;
        #pragma unroll
        for (int w = 0; w < TT; w++) {
            float acc = 0.f;
            #pragma unroll
            for (int j4 = 0; j4 < 4; j4++) {
                float4 cv = *(const float4*)&sC[bf][w][q4 + j4 * 16];
                acc = fmaf(cv.x, sin[j4 * 4],     acc);
                acc = fmaf(cv.y, sin[j4 * 4 + 1], acc);
                acc = fmaf(cv.z, sin[j4 * 4 + 2], acc);
                acc = fmaf(cv.w, sin[j4 * 4 + 3], acc);
            }
            acc += __shfl_xor_sync(0xffffffffu, acc, 1);
            acc += __shfl_xor_sync(0xffffffffu, acc, 2);
            if (quad == 0) {
                float wgt = __expf(A * scum[bf][w]);
                y[(size_t)(tbase + i * TT + w) * DINNER + h * DHEAD + p] += wgt * acc;
            }
        }
    }
}

// ---------------- gate (y * silu(z)) + rmsnorm + triplet split, float4 -------
__global__ void gate_norm_split_kernel(const float* __restrict__ zxbcdt,
                                       const float* __restrict__ y,
                                       const float* __restrict__ gw,
                                       __nv_bfloat16* __restrict__ O)
{
    int t = blockIdx.x;
    int tid = threadIdx.x;
    __shared__ float sv[DINNER];
    __shared__ float wsum[8];
    const float4* zr = (const float4*)(zxbcdt + (size_t)t * DINPROJ);
    const float4* yr = (const float4*)(y + (size_t)t * DINNER);
    float lsum = 0.f;
    #pragma unroll
    for (int it = 0; it < 2; it++) {
        int i4 = tid + it * 256;
        float4 z = zr[i4];
        float4 yv = yr[i4];
        float4 v;
        v.x = yv.x * (z.x / (1.f + __expf(-z.x)));
        v.y = yv.y * (z.y / (1.f + __expf(-z.y)));
        v.z = yv.z * (z.z / (1.f + __expf(-z.z)));
        v.w = yv.w * (z.w / (1.f + __expf(-z.w)));
        ((float4*)sv)[i4] = v;
        lsum += v.x * v.x + v.y * v.y + v.z * v.z + v.w * v.w;
    }
    int lane = tid & 31, wid = tid >> 5;
    #pragma unroll
    for (int off = 16; off > 0; off >>= 1)
        lsum += __shfl_xor_sync(0xffffffffu, lsum, off);
    if (lane == 0) wsum[wid] = lsum;
    __syncthreads();
    __shared__ float s_rs;
    if (tid == 0) {
        float tot = 0.f;
        for (int i = 0; i < 8; i++) tot += wsum[i];
        s_rs = rsqrtf(tot / (float)DINNER + EPSV);
    }
    __syncthreads();
    float rs = s_rs;
    __nv_bfloat16* obase = O + (size_t)t * (3 * DINNER);
    #pragma unroll
    for (int it = 0; it < 2; it++) {
        int i4 = tid + it * 256;
        float4 v = ((float4*)sv)[i4];
        float4 wv = ((const float4*)gw)[i4];
        float o[4] = {v.x * rs * wv.x, v.y * rs * wv.y, v.z * rs * wv.z, v.w * rs * wv.w};
        __nv_bfloat16 hi[4], lo[4];
        #pragma unroll
        for (int j = 0; j < 4; j++) {
            hi[j] = __float2bfloat16(o[j]);
            lo[j] = __float2bfloat16(o[j] - __bfloat162float(hi[j]));
        }
        __nv_bfloat16* orow = obase + i4 * 4;
        __nv_bfloat162* p0 = (__nv_bfloat162*)orow;
        __nv_bfloat162* p1 = (__nv_bfloat162*)(orow + DINNER);
        __nv_bfloat162* p2 = (__nv_bfloat162*)(orow + 2 * DINNER);
        p0[0] = __nv_bfloat162{hi[0], hi[1]};  p0[1] = __nv_bfloat162{hi[2], hi[3]};
        p1[0] = __nv_bfloat162{lo[0], lo[1]};  p1[1] = __nv_bfloat162{lo[2], lo[3]};
        p2[0] = __nv_bfloat162{hi[0], hi[1]};  p2[1] = __nv_bfloat162{hi[2], hi[3]};
    }
}

// ---------------- host orchestration ----------------
extern "C" void kernel_launch(void* const* d_in, const int* in_sizes, int n_in,
                              void* d_out, int out_size)
{
    const float* x        = (const float*)d_in[0];
    const float* in_w     = (const float*)d_in[1];
    const float* conv_w   = (const float*)d_in[2];
    const float* conv_b   = (const float*)d_in[3];
    const float* dt_bias  = (const float*)d_in[4];
    const float* A_log    = (const float*)d_in[5];
    const float* Dvec     = (const float*)d_in[6];
    const float* gnorm_w  = (const float*)d_in[7];
    const float* out_w    = (const float*)d_in[8];
    const float* rms_w    = (const float*)d_in[9];
    float* out = (float*)d_out;

    float *p_zx, *p_xc, *p_y, *p_sl, *p_si, *p_cd;
    __nv_bfloat16 *p_as, *p_bwin, *p_bwout;
    cudaGetSymbolAddress((void**)&p_zx, g_zxbcdt);
    cudaGetSymbolAddress((void**)&p_xc, g_xconv);
    cudaGetSymbolAddress((void**)&p_y,  g_y);
    cudaGetSymbolAddress((void**)&p_sl, g_Sloc);
    cudaGetSymbolAddress((void**)&p_si, g_Sin);
    cudaGetSymbolAddress((void**)&p_cd, g_cumdt);
    cudaGetSymbolAddress((void**)&p_as, g_asp);
    cudaGetSymbolAddress((void**)&p_bwin,  g_bw_in);
    cudaGetSymbolAddress((void**)&p_bwout, g_bw_out);

    cudaFuncSetAttribute(gemm_bf16_nt,
                         cudaFuncAttributeMaxDynamicSharedMemorySize, GEMM_SMEM_BYTES);

    cudaMemcpyAsync(out, x, (size_t)TTOT * DMODEL * sizeof(float),
                    cudaMemcpyDeviceToDevice);

    // all-layer weight splits, hoisted out of the layer loop (2 launches total)
    split_w_kernel<<<((size_t)NLAYERS * DINPROJ * DMODEL / 4 + 255) / 256, 256>>>(
        in_w, p_bwin, NLAYERS * DINPROJ, DMODEL);
    split_w_kernel<<<((size_t)NLAYERS * DMODEL * DINNER / 4 + 255) / 256, 256>>>(
        out_w, p_bwout, NLAYERS * DMODEL, DINNER);

    for (int layer = 0; layer < NLAYERS; layer++) {
        const __nv_bfloat16* lw_in_t  = p_bwin  + (size_t)layer * DINPROJ * 3 * DMODEL;
        const __nv_bfloat16* lw_out_t = p_bwout + (size_t)layer * DMODEL * 3 * DINNER;
        const float* lw_cw   = conv_w  + (size_t)layer * CONVDIM * DCONV;
        const float* lw_cb   = conv_b  + (size_t)layer * CONVDIM;
        const float* lw_dtb  = dt_bias + (size_t)layer * NHEADS;
        const float* lw_Alog = A_log   + (size_t)layer * NHEADS;
        const float* lw_D    = Dvec    + (size_t)layer * NHEADS;
        const float* lw_gn   = gnorm_w + (size_t)layer * DINNER;
        const float* lw_rms  = rms_w   + (size_t)layer * DMODEL;

        // 1. rmsnorm(x) -> bf16 triplet A operand
        rmsnorm_split_kernel<<<TTOT, 256>>>(out, lw_rms, p_as);

        // 2. in_proj
        {
            dim3 grid((DINPROJ + BN - 1) / BN, TTOT / BM);
            gemm_bf16_nt<<<grid, 256, GEMM_SMEM_BYTES>>>(p_as, lw_in_t, p_zx,
                                                         TTOT, DINPROJ, 3 * DMODEL, 0);
        }

        // 3. conv + silu (4 timesteps/thread)
        {
            int total = (TTOT / 4) * (CONVDIM / 4);
            conv_silu_kernel<<<(total + 255) / 256, 256>>>(p_zx, lw_cw, lw_cb, p_xc);
        }

        // 4. SSD: fused-dt chunked 3-phase scan
        ssd_local_kernel<<<BATCH * NHEADS * NCH, 256>>>(p_xc, p_zx, lw_dtb,
                                                        lw_Alog, lw_D,
                                                        p_y, p_sl, p_cd);
        ssd_combine_kernel<<<BATCH * NHEADS, 256>>>(p_sl, p_cd, lw_Alog, p_si);
        ssd_correct_kernel<<<BATCH * NHEADS * NCH, 256>>>(p_xc, p_cd, lw_Alog, p_si, p_y);

        // 5. gate + rmsnorm -> bf16 triplet A operand
        gate_norm_split_kernel<<<TTOT, 256>>>(p_zx, p_y, lw_gn, p_as);

        // 6. out_proj with residual add
        {
            dim3 grid(DMODEL / BN, TTOT / BM);
            gemm_bf16_nt<<<grid, 256, GEMM_SMEM_BYTES>>>(p_as, lw_out_t, out,
                                                         TTOT, DMODEL, 3 * DINNER, 1);
        }
    }
}

// round 14
// speedup vs baseline: 1.0296x; 1.0164x over previous
#include <cuda_runtime.h>
#include <cuda_bf16.h>
#include <math.h>
#include <stdint.h>

// ---------------- problem constants ----------------
#define BATCH     2
#define SEQ       2048
#define TTOT      (BATCH*SEQ)        // 4096
#define DMODEL    1024
#define DINNER    2048
#define DHEAD     64
#define NHEADS    32
#define DSTATE    64
#define DCONV     4
#define CONVDIM   (DINNER + 2*DSTATE)            // 2176
#define DINPROJ   (2*DINNER + 2*DSTATE + NHEADS) // 4256
#define NLAYERS   4
#define EPSV      1e-5f

#define CHL       128                 // scan chunk length
#define NCH       (SEQ/CHL)           // 16 chunks per sequence
#define TT        16                  // scan timestep tile
#define NTILES    (CHL/TT)            // 8

// ---------------- scratch (device globals; no allocs allowed) ----------------
__device__ float g_zxbcdt[(size_t)TTOT * DINPROJ];
__device__ float g_xconv[(size_t)TTOT * CONVDIM];
__device__ float g_y[(size_t)TTOT * DINNER];
// compact [hi|lo] bf16 operands (row stride = 2K); GEMM maps logical 3K -> 2K
__device__ __nv_bfloat16 g_asp[(size_t)TTOT * 2 * DINNER];
__device__ __nv_bfloat16 g_bw_in [(size_t)NLAYERS * DINPROJ * 2 * DMODEL];
__device__ __nv_bfloat16 g_bw_out[(size_t)NLAYERS * DMODEL * 2 * DINNER];
__device__ float g_Sloc[(size_t)BATCH*NHEADS*NCH * DHEAD * DSTATE];
__device__ float g_Sin [(size_t)BATCH*NHEADS*NCH * DHEAD * DSTATE];
__device__ float g_cumdt[(size_t)TTOT * NHEADS];

__device__ __forceinline__ uint32_t s2u(const void* p) {
    return (uint32_t)__cvta_generic_to_shared(p);
}

__device__ __forceinline__ float softplusf(float v) {
    return (v > 20.f) ? v : log1pf(__expf(v));
}

// =========== bf16 mma.sync NT GEMM: logical K' = 3K over [hi|lo] storage ====
// logical regions: 0 = Ahi*Bhi, 1 = Alo*Bhi, 2 = Ahi*Blo.
// storage: A row = [hi(K) | lo(K)], B row = [hi(K) | lo(K)], stride 2K.
// CTA tile 128x128, 8 warps (2x4), warp tile 64x32, BK=64, 3-stage cp.async.
#define BM 128
#define BN 128
#define BK 64
#define NSTG 3
#define STG_A 16384
#define STG_BYTES (2*STG_A)
#define GEMM_SMEM_BYTES (NSTG * STG_BYTES)   // 98304 B

__device__ __forceinline__ void gemm_issue(
    const __nv_bfloat16* __restrict__ A, const __nv_bfloat16* __restrict__ B,
    int N, int K, int m0, int n0, int kbase,
    char* As, char* Bs, int tid)
{
    // region mapping: cheap predicated adds (K is a multiple of BK)
    int offA = (kbase >= 2 * K) ? (kbase - 2 * K) : kbase;   // hi,lo,hi
    int offB = (kbase >= K)     ? (kbase - K)     : kbase;   // hi,hi,lo
    int K2 = 2 * K;
    #pragma unroll
    for (int it = 0; it < 4; it++) {
        int id  = tid + it * 256;
        int row = id >> 3;
        int ch  = id & 7;
        int sw  = ch ^ (row & 7);
        int dst = row * 128 + sw * 16;
        {
            uint32_t saddr = s2u(As + dst);
            const void* g = A + (size_t)(m0 + row) * K2 + offA + ch * 8;
            asm volatile("cp.async.cg.shared.global [%0], [%1], 16;"
                         :: "r"(saddr), "l"(g));
        }
        {
            uint32_t saddr = s2u(Bs + dst);
            int valid = (n0 + row) < N;
            const void* g = B + (valid ? ((size_t)(n0 + row) * K2 + offB + ch * 8) : 0);
            int sz = valid ? 16 : 0;
            asm volatile("cp.async.cg.shared.global [%0], [%1], 16, %2;"
                         :: "r"(saddr), "l"(g), "r"(sz));
        }
    }
}

__global__ __launch_bounds__(256, 2)
void gemm_bf16_nt(const __nv_bfloat16* __restrict__ A, const __nv_bfloat16* __restrict__ B,
                  float* __restrict__ C, int M, int N, int K, int addC)
{
    extern __shared__ __align__(16) char dynsmem[];

    int tid  = threadIdx.x;
    int lane = tid & 31;
    int wid  = tid >> 5;
    int m0 = blockIdx.y * BM;
    int n0 = blockIdx.x * BN;
    int wm = (wid & 1) * 64;
    int wn = (wid >> 1) * 32;

    float acc[4][4][4];
    #pragma unroll
    for (int a = 0; a < 4; a++)
        #pragma unroll
        for (int b = 0; b < 4; b++)
            #pragma unroll
            for (int c = 0; c < 4; c++) acc[a][b][c] = 0.f;

    int NT = (3 * K) / BK;

    #pragma unroll
    for (int s = 0; s < NSTG - 1; s++) {
        gemm_issue(A, B, N, K, m0, n0, s * BK,
                   dynsmem + s * STG_BYTES, dynsmem + s * STG_BYTES + STG_A, tid);
        asm volatile("cp.async.commit_group;" ::: "memory");
    }

    int sc = 0;
    int si = NSTG - 1;
    for (int kt = 0; kt < NT; kt++) {
        asm volatile("cp.async.wait_group 1;" ::: "memory");
        __syncthreads();
        if (kt + 2 < NT) {
            gemm_issue(A, B, N, K, m0, n0, (kt + 2) * BK,
                       dynsmem + si * STG_BYTES, dynsmem + si * STG_BYTES + STG_A, tid);
        }
        asm volatile("cp.async.commit_group;" ::: "memory");
        si = (si == NSTG - 1) ? 0 : si + 1;

        char* As = dynsmem + sc * STG_BYTES;
        char* Bs = As + STG_A;
        sc = (sc == NSTG - 1) ? 0 : sc + 1;

        #pragma unroll
        for (int ks = 0; ks < 4; ks++) {
            uint32_t af[4][4];
            uint32_t bf[4][2];
            #pragma unroll
            for (int mi = 0; mi < 4; mi++) {
                int row = wm + mi * 16 + (lane & 15);
                int ch  = ks * 2 + (lane >> 4);
                int sw  = ch ^ (row & 7);
                uint32_t addr = s2u(As + row * 128 + sw * 16);
                asm volatile("ldmatrix.sync.aligned.m8n8.x4.shared.b16 {%0,%1,%2,%3}, [%4];"
                             : "=r"(af[mi][0]), "=r"(af[mi][1]),
                               "=r"(af[mi][2]), "=r"(af[mi][3])
                             : "r"(addr));
            }
            #pragma unroll
            for (int nj = 0; nj < 4; nj += 2) {
                int row = wn + nj * 8 + (lane >> 4) * 8 + (lane & 7);
                int ch  = ks * 2 + ((lane >> 3) & 1);
                int sw  = ch ^ (row & 7);
                uint32_t addr = s2u(Bs + row * 128 + sw * 16);
                asm volatile("ldmatrix.sync.aligned.m8n8.x4.shared.b16 {%0,%1,%2,%3}, [%4];"
                             : "=r"(bf[nj][0]), "=r"(bf[nj][1]),
                               "=r"(bf[nj + 1][0]), "=r"(bf[nj + 1][1])
                             : "r"(addr));
            }
            #pragma unroll
            for (int mi = 0; mi < 4; mi++)
                #pragma unroll
                for (int nj = 0; nj < 4; nj++)
                    asm volatile(
                        "mma.sync.aligned.m16n8k16.row.col.f32.bf16.bf16.f32 "
                        "{%0,%1,%2,%3}, {%4,%5,%6,%7}, {%8,%9}, {%0,%1,%2,%3};"
                        : "+f"(acc[mi][nj][0]), "+f"(acc[mi][nj][1]),
                          "+f"(acc[mi][nj][2]), "+f"(acc[mi][nj][3])
                        : "r"(af[mi][0]), "r"(af[mi][1]),
                          "r"(af[mi][2]), "r"(af[mi][3]),
                          "r"(bf[nj][0]), "r"(bf[nj][1]));
        }
    }

    #pragma unroll
    for (int mi = 0; mi < 4; mi++) {
        int r0 = m0 + wm + mi * 16 + (lane >> 2);
        #pragma unroll
        for (int nj = 0; nj < 4; nj++) {
            int c0 = n0 + wn + nj * 8 + (lane & 3) * 2;
            if (c0 < N) {
                float2* p0 = (float2*)(C + (size_t)r0 * N + c0);
                float2* p1 = (float2*)(C + (size_t)(r0 + 8) * N + c0);
                float2 v0 = make_float2(acc[mi][nj][0], acc[mi][nj][1]);
                float2 v1 = make_float2(acc[mi][nj][2], acc[mi][nj][3]);
                if (addC) {
                    float2 o0 = *p0, o1 = *p1;
                    v0.x += o0.x; v0.y += o0.y;
                    v1.x += o1.x; v1.y += o1.y;
                }
                *p0 = v0;
                *p1 = v1;
            }
        }
    }
}

// ---------------- rmsnorm + [hi|lo] split, float4 ----------------
__global__ void rmsnorm_split_kernel(const float* __restrict__ x,
                                     const float* __restrict__ w,
                                     __nv_bfloat16* __restrict__ O)
{
    int t = blockIdx.x;
    int tid = threadIdx.x;
    const float4* xr4 = (const float4*)(x + (size_t)t * DMODEL);
    float4 v = xr4[tid];
    float lsum = v.x * v.x + v.y * v.y + v.z * v.z + v.w * v.w;

    __shared__ float wsum[8];
    int lane = tid & 31, wid = tid >> 5;
    #pragma unroll
    for (int off = 16; off > 0; off >>= 1)
        lsum += __shfl_xor_sync(0xffffffffu, lsum, off);
    if (lane == 0) wsum[wid] = lsum;
    __syncthreads();
    __shared__ float s_rs;
    if (tid == 0) {
        float tot = 0.f;
        for (int i = 0; i < 8; i++) tot += wsum[i];
        s_rs = rsqrtf(tot / (float)DMODEL + EPSV);
    }
    __syncthreads();
    float rs = s_rs;
    float4 wv = ((const float4*)w)[tid];
    float o[4] = {v.x * rs * wv.x, v.y * rs * wv.y, v.z * rs * wv.z, v.w * rs * wv.w};
    __nv_bfloat16 hi[4], lo[4];
    #pragma unroll
    for (int j = 0; j < 4; j++) {
        hi[j] = __float2bfloat16(o[j]);
        lo[j] = __float2bfloat16(o[j] - __bfloat162float(hi[j]));
    }
    __nv_bfloat16* orow = O + (size_t)t * (2 * DMODEL) + tid * 4;
    __nv_bfloat162* p0 = (__nv_bfloat162*)orow;
    __nv_bfloat162* p1 = (__nv_bfloat162*)(orow + DMODEL);
    p0[0] = __nv_bfloat162{hi[0], hi[1]};  p0[1] = __nv_bfloat162{hi[2], hi[3]};
    p1[0] = __nv_bfloat162{lo[0], lo[1]};  p1[1] = __nv_bfloat162{lo[2], lo[3]};
}

// ---------------- weight split: fp32 -> [hi | lo], float4 ----------
__global__ void split_w_kernel(const float* __restrict__ X, __nv_bfloat16* __restrict__ O,
                               int rows, int K)
{
    int i4 = blockIdx.x * blockDim.x + threadIdx.x;
    int kq = K >> 2;
    if (i4 >= rows * kq) return;
    int r = i4 / kq;
    int k = (i4 - r * kq) * 4;
    float4 x = ((const float4*)X)[i4];
    float xv[4] = {x.x, x.y, x.z, x.w};
    __nv_bfloat16 hi[4], lo[4];
    #pragma unroll
    for (int j = 0; j < 4; j++) {
        hi[j] = __float2bfloat16(xv[j]);
        lo[j] = __float2bfloat16(xv[j] - __bfloat162float(hi[j]));
    }
    __nv_bfloat16* orow = O + (size_t)r * (2 * K) + k;
    __nv_bfloat162* p0 = (__nv_bfloat162*)orow;
    __nv_bfloat162* p1 = (__nv_bfloat162*)(orow + K);
    p0[0] = __nv_bfloat162{hi[0], hi[1]};  p0[1] = __nv_bfloat162{hi[2], hi[3]};
    p1[0] = __nv_bfloat162{lo[0], lo[1]};  p1[1] = __nv_bfloat162{lo[2], lo[3]};
}

// ---------------- depthwise conv(4) + silu: 4 timesteps per thread ----------
__global__ void conv_silu_kernel(const float* __restrict__ zxbcdt,
                                 const float* __restrict__ cw,
                                 const float* __restrict__ cb,
                                 float* __restrict__ xconv)
{
    const int NC4 = CONVDIM / 4;
    int i = blockIdx.x * blockDim.x + threadIdx.x;
    if (i >= (TTOT / 4) * NC4) return;
    int c4 = i % NC4;
    int tp = i / NC4;
    int b  = tp / (SEQ / 4);
    int l0 = (tp % (SEQ / 4)) * 4;
    int ch = c4 * 4;

    float wk[DCONV][4];
    #pragma unroll
    for (int j = 0; j < 4; j++) {
        float4 w = *(const float4*)(cw + (ch + j) * DCONV);
        wk[0][j] = w.x; wk[1][j] = w.y; wk[2][j] = w.z; wk[3][j] = w.w;
    }
    float4 bb = *(const float4*)(cb + ch);

    float4 in[7];
    #pragma unroll
    for (int k = 0; k < 7; k++) {
        int ll = l0 - 3 + k;
        if (ll >= 0)
            in[k] = *(const float4*)(zxbcdt + (size_t)(b * SEQ + ll) * DINPROJ + DINNER + ch);
        else
            in[k] = make_float4(0.f, 0.f, 0.f, 0.f);
    }

    #pragma unroll
    for (int o = 0; o < 4; o++) {
        float a[4] = {bb.x, bb.y, bb.z, bb.w};
        #pragma unroll
        for (int k = 0; k < DCONV; k++) {
            float* vp = (float*)&in[o + k];
            #pragma unroll
            for (int j = 0; j < 4; j++)
                a[j] = fmaf(vp[j], wk[k][j], a[j]);
        }
        float4 ov;
        ov.x = a[0] / (1.f + __expf(-a[0]));
        ov.y = a[1] / (1.f + __expf(-a[1]));
        ov.z = a[2] / (1.f + __expf(-a[2]));
        ov.w = a[3] / (1.f + __expf(-a[3]));
        *(float4*)(xconv + (size_t)(b * SEQ + l0 + o) * CONVDIM + ch) = ov;
    }
}

// ---------------- SSD phase A: fused dt + triple-buffered local scan --------
// TT=16: halved barrier count vs TT=8.
__device__ __forceinline__ void ssd_local_issue(
    const float* __restrict__ xconv, const float* __restrict__ zxbcdt,
    int tbase, int t0, int h,
    float* sBC, float* sX, float* sdtraw, int tid)
{
    #pragma unroll
    for (int it = 0; it < 2; it++) {   // BC: 16 timesteps x 32 chunks of 16B
        int id = tid + it * 256;
        int w = id >> 5, ch = id & 31;
        const void* g = xconv + (size_t)(tbase + t0 + w) * CONVDIM + DINNER + ch * 4;
        asm volatile("cp.async.cg.shared.global [%0], [%1], 16;"
                     :: "r"(s2u(sBC + w * 128 + ch * 4)), "l"(g));
    }
    {   // X: 16 timesteps x 16 chunks
        int w = tid >> 4, ch = tid & 15;
        const void* g = xconv + (size_t)(tbase + t0 + w) * CONVDIM + h * DHEAD + ch * 4;
        asm volatile("cp.async.cg.shared.global [%0], [%1], 16;"
                     :: "r"(s2u(sX + w * 64 + ch * 4)), "l"(g));
    }
    if (tid < TT) {
        const void* g = zxbcdt + (size_t)(tbase + t0 + tid) * DINPROJ
                        + (DINPROJ - NHEADS) + h;
        asm volatile("cp.async.ca.shared.global [%0], [%1], 4;"
                     :: "r"(s2u(sdtraw + tid)), "l"(g));
    }
}

__global__ __launch_bounds__(256, 4)
void ssd_local_kernel(const float* __restrict__ xconv,
                      const float* __restrict__ zxbcdt,
                      const float* __restrict__ dt_bias,
                      const float* __restrict__ A_log,
                      const float* __restrict__ Dvec,
                      float* __restrict__ y,
                      float* __restrict__ Sloc,
                      float* __restrict__ cumdt)
{
    int bhc = blockIdx.x;
    int c = bhc & (NCH - 1);
    int h = (bhc >> 4) & 31;
    int b = bhc >> 9;
    float A    = -__expf(A_log[h]);
    float Dh   = Dvec[h];
    float bias = dt_bias[h];
    int tid  = threadIdx.x;
    int p    = tid >> 2;
    int quad = tid & 3;
    int q4   = quad * 4;

    __shared__ float sBC[3][TT][128];
    __shared__ float sX[3][TT][DHEAD];
    __shared__ float sdtraw[3][TT];

    float s[16];
    #pragma unroll
    for (int j = 0; j < 16; j++) s[j] = 0.f;
    float cum = 0.f;
    int tbase = b * SEQ + c * CHL;

    ssd_local_issue(xconv, zxbcdt, tbase, 0, h,
                    &sBC[0][0][0], &sX[0][0][0], sdtraw[0], tid);
    asm volatile("cp.async.commit_group;" ::: "memory");

    for (int i = 0; i < NTILES; i++) {
        if (i + 1 < NTILES) {
            int nb = (i + 1) % 3;
            ssd_local_issue(xconv, zxbcdt, tbase, (i + 1) * TT, h,
                            &sBC[nb][0][0], &sX[nb][0][0], sdtraw[nb], tid);
        }
        asm volatile("cp.async.commit_group;" ::: "memory");
        asm volatile("cp.async.wait_group 1;" ::: "memory");
        __syncthreads();

        int bf = i % 3;
        if (tid == 0) {
            float cc = cum;
            #pragma unroll
            for (int w = 0; w < TT; w++) {
                cc += softplusf(sdtraw[bf][w] + bias);
                cumdt[(size_t)(tbase + i * TT + w) * NHEADS + h] = cc;
            }
            cum = cc;
        }

        #pragma unroll
        for (int w = 0; w < TT; w++) {
            float dts = softplusf(sdtraw[bf][w] + bias);
            float da  = __expf(dts * A);
            float xp  = sX[bf][w][p] * dts;
            float accv = 0.f;
            #pragma unroll
            for (int j4 = 0; j4 < 4; j4++) {
                float4 bv = *(const float4*)&sBC[bf][w][q4 + j4 * 16];
                float4 cv = *(const float4*)&sBC[bf][w][64 + q4 + j4 * 16];
                float* bvp = (float*)&bv;
                float* cvp = (float*)&cv;
                #pragma unroll
                for (int jj = 0; jj < 4; jj++) {
                    int idx = j4 * 4 + jj;
                    s[idx] = fmaf(da, s[idx], xp * bvp[jj]);
                    accv   = fmaf(cvp[jj], s[idx], accv);
                }
            }
            accv += __shfl_xor_sync(0xffffffffu, accv, 1);
            accv += __shfl_xor_sync(0xffffffffu, accv, 2);
            if (quad == 0)
                y[(size_t)(tbase + i * TT + w) * DINNER + h * DHEAD + p]
                    = accv + Dh * sX[bf][w][p];
        }
    }

    float* sl = Sloc + ((size_t)bhc * DHEAD + p) * DSTATE + q4;
    #pragma unroll
    for (int j4 = 0; j4 < 4; j4++)
        *(float4*)(sl + j4 * 16) = make_float4(s[j4 * 4], s[j4 * 4 + 1],
                                               s[j4 * 4 + 2], s[j4 * 4 + 3]);
}

// ---------------- SSD phase B: sequential carry combine over chunks ----------
__global__ void ssd_combine_kernel(const float* __restrict__ Sloc,
                                   const float* __restrict__ cumdt,
                                   const float* __restrict__ A_log,
                                   float* __restrict__ Sin)
{
    int bh = blockIdx.x;
    int b = bh >> 5, h = bh & 31;
    float A = -__expf(A_log[h]);
    int tid = threadIdx.x;
    int p = tid >> 2, quad = tid & 3;
    int q4 = quad * 4;

    float4 s[4];
    #pragma unroll
    for (int j4 = 0; j4 < 4; j4++) s[j4] = make_float4(0.f, 0.f, 0.f, 0.f);

    for (int c = 0; c < NCH; c++) {
        size_t base = (((size_t)(b * 512 + h * 16 + c)) * DHEAD + p) * DSTATE + q4;
        float dec = __expf(A * cumdt[(size_t)(b * SEQ + c * CHL + CHL - 1) * NHEADS + h]);
        #pragma unroll
        for (int j4 = 0; j4 < 4; j4++) {
            float4 sl = *(const float4*)(Sloc + base + j4 * 16);
            *(float4*)(Sin + base + j4 * 16) = s[j4];
            s[j4].x = fmaf(dec, s[j4].x, sl.x);
            s[j4].y = fmaf(dec, s[j4].y, sl.y);
            s[j4].z = fmaf(dec, s[j4].z, sl.z);
            s[j4].w = fmaf(dec, s[j4].w, sl.w);
        }
    }
}

// ---------------- SSD phase C: triple-buffered cross-chunk correction -------
__device__ __forceinline__ void ssd_corr_issue(
    const float* __restrict__ xconv, const float* __restrict__ cumdt,
    int tbase, int t0, int h, float* sC, float* scum, int tid)
{
    {   // C: 16 timesteps x 16 chunks of 16B
        int w = tid >> 4, ch = tid & 15;
        const void* g = xconv + (size_t)(tbase + t0 + w) * CONVDIM
                        + DINNER + DSTATE + ch * 4;
        asm volatile("cp.async.cg.shared.global [%0], [%1], 16;"
                     :: "r"(s2u(sC + w * 64 + ch * 4)), "l"(g));
    }
    if (tid < TT) {
        const void* g = cumdt + (size_t)(tbase + t0 + tid) * NHEADS + h;
        asm volatile("cp.async.ca.shared.global [%0], [%1], 4;"
                     :: "r"(s2u(scum + tid)), "l"(g));
    }
}

__global__ __launch_bounds__(256, 4)
void ssd_correct_kernel(const float* __restrict__ xconv,
                        const float* __restrict__ cumdt,
                        const float* __restrict__ A_log,
                        const float* __restrict__ Sin,
                        float* __restrict__ y)
{
    int bhc = blockIdx.x;
    int c = bhc & (NCH - 1);
    if (c == 0) return;
    int h = (bhc >> 4) & 31;
    int b = bhc >> 9;
    float A = -__expf(A_log[h]);
    int tid = threadIdx.x;
    int p = tid >> 2, quad = tid & 3;
    int q4 = quad * 4;

    float sin[16];
    {
        const float* sp = Sin + ((size_t)bhc * DHEAD + p) * DSTATE + q4;
        #pragma unroll
        for (int j4 = 0; j4 < 4; j4++) {
            float4 v = *(const float4*)(sp + j4 * 16);
            sin[j4 * 4]     = v.x;
            sin[j4 * 4 + 1] = v.y;
            sin[j4 * 4 + 2] = v.z;
            sin[j4 * 4 + 3] = v.w;
        }
    }

    __shared__ float sC[3][TT][DSTATE];
    __shared__ float scum[3][TT];
    int tbase = b * SEQ + c * CHL;

    ssd_corr_issue(xconv, cumdt, tbase, 0, h, &sC[0][0][0], scum[0], tid);
    asm volatile("cp.async.commit_group;" ::: "memory");

    for (int i = 0; i < NTILES; i++) {
        if (i + 1 < NTILES) {
            int nb = (i + 1) % 3;
            ssd_corr_issue(xconv, cumdt, tbase, (i + 1) * TT, h,
                           &sC[nb][0][0], scum[nb], tid);
        }
        asm volatile("cp.async.commit_group;" ::: "memory");
        asm volatile("cp.async.wait_group 1;" ::: "memory");
        __syncthreads();

        int bf = i % 3;
        #pragma unroll
        for (int w = 0; w < TT; w++) {
            float acc = 0.f;
            #pragma unroll
            for (int j4 = 0; j4 < 4; j4++) {
                float4 cv = *(const float4*)&sC[bf][w][q4 + j4 * 16];
                acc = fmaf(cv.x, sin[j4 * 4],     acc);
                acc = fmaf(cv.y, sin[j4 * 4 + 1], acc);
                acc = fmaf(cv.z, sin[j4 * 4 + 2], acc);
                acc = fmaf(cv.w, sin[j4 * 4 + 3], acc);
            }
            acc += __shfl_xor_sync(0xffffffffu, acc, 1);
            acc += __shfl_xor_sync(0xffffffffu, acc, 2);
            if (quad == 0) {
                float wgt = __expf(A * scum[bf][w]);
                y[(size_t)(tbase + i * TT + w) * DINNER + h * DHEAD + p] += wgt * acc;
            }
        }
    }
}

// ---------------- gate (y * silu(z)) + rmsnorm + [hi|lo] split, float4 -------
__global__ void gate_norm_split_kernel(const float* __restrict__ zxbcdt,
                                       const float* __restrict__ y,
                                       const float* __restrict__ gw,
                                       __nv_bfloat16* __restrict__ O)
{
    int t = blockIdx.x;
    int tid = threadIdx.x;
    __shared__ float sv[DINNER];
    __shared__ float wsum[8];
    const float4* zr = (const float4*)(zxbcdt + (size_t)t * DINPROJ);
    const float4* yr = (const float4*)(y + (size_t)t * DINNER);
    float lsum = 0.f;
    #pragma unroll
    for (int it = 0; it < 2; it++) {
        int i4 = tid + it * 256;
        float4 z = zr[i4];
        float4 yv = yr[i4];
        float4 v;
        v.x = yv.x * (z.x / (1.f + __expf(-z.x)));
        v.y = yv.y * (z.y / (1.f + __expf(-z.y)));
        v.z = yv.z * (z.z / (1.f + __expf(-z.z)));
        v.w = yv.w * (z.w / (1.f + __expf(-z.w)));
        ((float4*)sv)[i4] = v;
        lsum += v.x * v.x + v.y * v.y + v.z * v.z + v.w * v.w;
    }
    int lane = tid & 31, wid = tid >> 5;
    #pragma unroll
    for (int off = 16; off > 0; off >>= 1)
        lsum += __shfl_xor_sync(0xffffffffu, lsum, off);
    if (lane == 0) wsum[wid] = lsum;
    __syncthreads();
    __shared__ float s_rs;
    if (tid == 0) {
        float tot = 0.f;
        for (int i = 0; i < 8; i++) tot += wsum[i];
        s_rs = rsqrtf(tot / (float)DINNER + EPSV);
    }
    __syncthreads();
    float rs = s_rs;
    __nv_bfloat16* obase = O + (size_t)t * (2 * DINNER);
    #pragma unroll
    for (int it = 0; it < 2; it++) {
        int i4 = tid + it * 256;
        float4 v = ((float4*)sv)[i4];
        float4 wv = ((const float4*)gw)[i4];
        float o[4] = {v.x * rs * wv.x, v.y * rs * wv.y, v.z * rs * wv.z, v.w * rs * wv.w};
        __nv_bfloat16 hi[4], lo[4];
        #pragma unroll
        for (int j = 0; j < 4; j++) {
            hi[j] = __float2bfloat16(o[j]);
            lo[j] = __float2bfloat16(o[j] - __bfloat162float(hi[j]));
        }
        __nv_bfloat16* orow = obase + i4 * 4;
        __nv_bfloat162* p0 = (__nv_bfloat162*)orow;
        __nv_bfloat162* p1 = (__nv_bfloat162*)(orow + DINNER);
        p0[0] = __nv_bfloat162{hi[0], hi[1]};  p0[1] = __nv_bfloat162{hi[2], hi[3]};
        p1[0] = __nv_bfloat162{lo[0], lo[1]};  p1[1] = __nv_bfloat162{lo[2], lo[3]};
    }
}

// ---------------- host orchestration ----------------
extern "C" void kernel_launch(void* const* d_in, const int* in_sizes, int n_in,
                              void* d_out, int out_size)
{
    const float* x        = (const float*)d_in[0];
    const float* in_w     = (const float*)d_in[1];
    const float* conv_w   = (const float*)d_in[2];
    const float* conv_b   = (const float*)d_in[3];
    const float* dt_bias  = (const float*)d_in[4];
    const float* A_log    = (const float*)d_in[5];
    const float* Dvec     = (const float*)d_in[6];
    const float* gnorm_w  = (const float*)d_in[7];
    const float* out_w    = (const float*)d_in[8];
    const float* rms_w    = (const float*)d_in[9];
    float* out = (float*)d_out;

    float *p_zx, *p_xc, *p_y, *p_sl, *p_si, *p_cd;
    __nv_bfloat16 *p_as, *p_bwin, *p_bwout;
    cudaGetSymbolAddress((void**)&p_zx, g_zxbcdt);
    cudaGetSymbolAddress((void**)&p_xc, g_xconv);
    cudaGetSymbolAddress((void**)&p_y,  g_y);
    cudaGetSymbolAddress((void**)&p_sl, g_Sloc);
    cudaGetSymbolAddress((void**)&p_si, g_Sin);
    cudaGetSymbolAddress((void**)&p_cd, g_cumdt);
    cudaGetSymbolAddress((void**)&p_as, g_asp);
    cudaGetSymbolAddress((void**)&p_bwin,  g_bw_in);
    cudaGetSymbolAddress((void**)&p_bwout, g_bw_out);

    cudaFuncSetAttribute(gemm_bf16_nt,
                         cudaFuncAttributeMaxDynamicSharedMemorySize, GEMM_SMEM_BYTES);

    cudaMemcpyAsync(out, x, (size_t)TTOT * DMODEL * sizeof(float),
                    cudaMemcpyDeviceToDevice);

    // all-layer weight splits (2 launches total)
    split_w_kernel<<<((size_t)NLAYERS * DINPROJ * DMODEL / 4 + 255) / 256, 256>>>(
        in_w, p_bwin, NLAYERS * DINPROJ, DMODEL);
    split_w_kernel<<<((size_t)NLAYERS * DMODEL * DINNER / 4 + 255) / 256, 256>>>(
        out_w, p_bwout, NLAYERS * DMODEL, DINNER);

    for (int layer = 0; layer < NLAYERS; layer++) {
        const __nv_bfloat16* lw_in_t  = p_bwin  + (size_t)layer * DINPROJ * 2 * DMODEL;
        const __nv_bfloat16* lw_out_t = p_bwout + (size_t)layer * DMODEL * 2 * DINNER;
        const float* lw_cw   = conv_w  + (size_t)layer * CONVDIM * DCONV;
        const float* lw_cb   = conv_b  + (size_t)layer * CONVDIM;
        const float* lw_dtb  = dt_bias + (size_t)layer * NHEADS;
        const float* lw_Alog = A_log   + (size_t)layer * NHEADS;
        const float* lw_D    = Dvec    + (size_t)layer * NHEADS;
        const float* lw_gn   = gnorm_w + (size_t)layer * DINNER;
        const float* lw_rms  = rms_w   + (size_t)layer * DMODEL;

        // 1. rmsnorm(x) -> [hi|lo] A operand
        rmsnorm_split_kernel<<<TTOT, 256>>>(out, lw_rms, p_as);

        // 2. in_proj (logical K' = 3*DMODEL over compact storage)
        {
            dim3 grid((DINPROJ + BN - 1) / BN, TTOT / BM);
            gemm_bf16_nt<<<grid, 256, GEMM_SMEM_BYTES>>>(p_as, lw_in_t, p_zx,
                                                         TTOT, DINPROJ, DMODEL, 0);
        }

        // 3. conv + silu (4 timesteps/thread)
        {
            int total = (TTOT / 4) * (CONVDIM / 4);
            conv_silu_kernel<<<(total + 255) / 256, 256>>>(p_zx, lw_cw, lw_cb, p_xc);
        }

        // 4. SSD: fused-dt chunked 3-phase scan (TT=16)
        ssd_local_kernel<<<BATCH * NHEADS * NCH, 256>>>(p_xc, p_zx, lw_dtb,
                                                        lw_Alog, lw_D,
                                                        p_y, p_sl, p_cd);
        ssd_combine_kernel<<<BATCH * NHEADS, 256>>>(p_sl, p_cd, lw_Alog, p_si);
        ssd_correct_kernel<<<BATCH * NHEADS * NCH, 256>>>(p_xc, p_cd, lw_Alog, p_si, p_y);

        // 5. gate + rmsnorm -> [hi|lo] A operand
        gate_norm_split_kernel<<<TTOT, 256>>>(p_zx, p_y, lw_gn, p_as);

        // 6. out_proj with residual add (logical K' = 3*DINNER)
        {
            dim3 grid(DMODEL / BN, TTOT / BM);
            gemm_bf16_nt<<<grid, 256, GEMM_SMEM_BYTES>>>(p_as, lw_out_t, out,
                                                         TTOT, DMODEL, DINNER, 1);
        }
    }
}